// round 8
// baseline (speedup 1.0000x reference)
#include <cuda_runtime.h>
#include <cuda_fp16.h>
#include <math.h>
#include <stdint.h>

// ---------------------------------------------------------------------------
// Problem constants
#define BN_   256   // batch
#define TN_   256   // time steps
#define DN_   300   // input dim
#define HN_   512   // hidden
#define XPAD  320   // x padded to 320 (5 chunks of 64)
#define KPAD  832   // 320 + 512 (W layout rows)
#define NCHX  5     // x chunks (precompute GEMM)
#define NCHS  8     // h chunks (per-step GEMM, K=512)
#define FOURH 2048

// ---------------------------------------------------------------------------
// Scratch (device globals)
__device__ __half g_xhi[2ll * BN_ * TN_ * XPAD];
__device__ __half g_xlo[2ll * BN_ * TN_ * XPAD];
__device__ __half g_whi[4ll * FOURH * KPAD];
__device__ __half g_wlo[4ll * FOURH * KPAD];
__device__ float  g_bp [4 * FOURH];                 // permuted bias
__device__ __half g_hhi[2ll * 4 * BN_ * HN_];       // double-buffered h hi
__device__ __half g_hlo[2ll * 4 * BN_ * HN_];       // double-buffered h lo
__device__ float  g_c  [4][BN_][HN_];               // cell state
__device__ float  g_x  [BN_ * FOURH];               // concat c -> MLP input
__device__ float  g_m1[BN_ * 1024];
__device__ float  g_m2[BN_ * 1024];
__device__ float  g_m3[BN_ * 1024];

// Precomputed x-projections: xz[seqpair][t][b][n], fp32 (two 1 GiB arrays)
#define XZ_PER (2ll * TN_ * BN_ * FOURH)
__device__ float g_xzA[XZ_PER];
__device__ float g_xzB[XZ_PER];

__device__ __forceinline__ float sigmoidf_(float v) { return 1.0f / (1.0f + expf(-v)); }

__device__ __forceinline__ uint32_t smem_u32(const void* p) {
    uint32_t a;
    asm("{ .reg .u64 t; cvta.to.shared.u64 t, %1; cvt.u32.u64 %0, t; }" : "=r"(a) : "l"(p));
    return a;
}
__device__ __forceinline__ void cp16(uint32_t dst, const void* src) {
    asm volatile("cp.async.cg.shared.global [%0], [%1], 16;" :: "r"(dst), "l"(src));
}
#define CP_COMMIT() asm volatile("cp.async.commit_group;" ::: "memory")
#define CP_WAIT(N)  asm volatile("cp.async.wait_group %0;" :: "n"(N) : "memory")

#define LDSM_X4(r0, r1, r2, r3, addr)                                         \
    asm volatile("ldmatrix.sync.aligned.m8n8.x4.shared.b16 {%0,%1,%2,%3}, [%4];" \
        : "=r"(r0), "=r"(r1), "=r"(r2), "=r"(r3) : "r"(addr))

// f32-accumulate HMMA (main product)
#define MMA16816(d, a, b)                                                     \
    asm volatile("mma.sync.aligned.m16n8k16.row.col.f32.f16.f16.f32 "         \
        "{%0,%1,%2,%3}, {%4,%5,%6,%7}, {%8,%9}, {%0,%1,%2,%3};"               \
        : "+f"((d)[0]), "+f"((d)[1]), "+f"((d)[2]), "+f"((d)[3])              \
        : "r"((a)[0]), "r"((a)[1]), "r"((a)[2]), "r"((a)[3]),                 \
          "r"((b)[0]), "r"((b)[1]))

// f16-accumulate HMMA (correction products)
#define MMA16816H(d, a, b)                                                    \
    asm volatile("mma.sync.aligned.m16n8k16.row.col.f16.f16.f16.f16 "         \
        "{%0,%1}, {%2,%3,%4,%5}, {%6,%7}, {%0,%1};"                           \
        : "+r"((d)[0]), "+r"((d)[1])                                          \
        : "r"((a)[0]), "r"((a)[1]), "r"((a)[2]), "r"((a)[3]),                 \
          "r"((b)[0]), "r"((b)[1]))

// ---------------------------------------------------------------------------
// Fused one-shot preprocessing (single launch)
struct WPtrs { const float* wx[4]; const float* wh[4]; const float* bias[4]; };

#define NXE_ (2ll * BN_ * TN_ * XPAD)
#define NWE_ (4ll * FOURH * KPAD)
#define NHE_ (2ll * 4 * BN_ * HN_)
#define NCE_ (4ll * BN_ * HN_)
#define NBE_ (4ll * FOURH)
#define NTOT_ (NXE_ + NWE_ + NHE_ + NCE_ + NBE_)

__global__ void preproc_all(const float* __restrict__ prem, const float* __restrict__ hyp,
                            WPtrs wp) {
    long long i = (long long)blockIdx.x * blockDim.x + threadIdx.x;
    if (i < NXE_) {
        int k = (int)(i % XPAD);
        long long r = i / XPAD;
        int t = (int)(r % TN_); r /= TN_;
        int b = (int)(r % BN_);
        int inp = (int)(r / BN_);
        float v = 0.0f;
        if (k < DN_) {
            const float* src = inp ? hyp : prem;
            v = src[((long long)b * TN_ + t) * DN_ + k];
        }
        __half h = __float2half(v);
        g_xhi[i] = h;
        g_xlo[i] = __float2half(v - __half2float(h));
        return;
    }
    i -= NXE_;
    if (i < NWE_) {
        int kp = (int)(i % KPAD);
        long long r = i / KPAD;
        int c   = (int)(r % FOURH);
        int seq = (int)(r / FOURH);
        int oc  = (c & 3) * HN_ + (c >> 2);          // gate-interleaved col' = u*4+g
        float v = 0.0f;
        if (kp < DN_)        v = wp.wx[seq][(long long)kp * FOURH + oc];
        else if (kp >= XPAD) v = wp.wh[seq][(long long)(kp - XPAD) * FOURH + oc];
        __half h = __float2half(v);
        g_whi[i] = h;
        g_wlo[i] = __float2half(v - __half2float(h));
        return;
    }
    i -= NWE_;
    if (i < NHE_) {
        g_hhi[i] = __float2half(0.f);
        g_hlo[i] = __float2half(0.f);
        return;
    }
    i -= NHE_;
    if (i < NCE_) {
        (&g_c[0][0][0])[i] = 0.0f;
        return;
    }
    i -= NCE_;
    if (i < NBE_) {
        int c = (int)(i & (FOURH - 1));
        int seq = (int)(i >> 11);
        g_bp[i] = wp.bias[seq][(c & 3) * HN_ + (c >> 2)];
    }
}

// ---------------------------------------------------------------------------
// xz precompute GEMM: xz[seq][t][b][n] = x[b,t,:] @ Wx_seq (fp16 hi/lo split).
// Tile 128(b) x 64(n), 256 threads = 8 warps (4m x 2n), warp tile 32x32.
#define XST_BYTES 49152
#define XOFF_AL   16384
#define XOFF_BH   32768
#define XOFF_BL   40960
#define SMEM_XZ   98304

__global__ __launch_bounds__(256) void xz_gemm() {
    extern __shared__ char smem[];
    const uint32_t sbase = smem_u32(smem);
    const int tid  = threadIdx.x;
    const int lane = tid & 31;
    const int wid  = tid >> 5;
    const int warp_m = wid >> 1;       // 0..3
    const int warp_n = wid & 1;        // 0..1

    const int z   = blockIdx.z;        // seq*TN_ + t
    const int seq = z >> 8;
    const int t   = z & 255;
    const int inp = seq >> 1;
    const int b0  = blockIdx.y * 128;
    const int n0  = blockIdx.x * 64;

    auto load_chunk = [&](int k, int p) {
        const uint32_t st = sbase + (p ? XST_BYTES : 0);
        const int k0 = k * 64;
        #pragma unroll
        for (int j = 0; j < 4; j++) {           // A: 1024 segs, hi + lo
            int idx = tid + 256 * j;
            int row = idx >> 3;
            int seg = idx & 7;
            long base = ((long)(inp * BN_ + b0 + row) * TN_ + t) * XPAD + k0 + seg * 8;
            uint32_t dst = st + ((row * 8 + (seg ^ (row & 7))) << 4);
            cp16(dst,           g_xhi + base);
            cp16(dst + XOFF_AL, g_xlo + base);
        }
        #pragma unroll
        for (int j = 0; j < 2; j++) {           // B: 512 segs, hi + lo
            int idx = tid + 256 * j;
            int row = idx >> 3;
            int seg = idx & 7;
            long base = ((long)seq * FOURH + n0 + row) * KPAD + k0 + seg * 8;
            uint32_t dst = st + XOFF_BH + ((row * 8 + (seg ^ (row & 7))) << 4);
            cp16(dst,        g_whi + base);
            cp16(dst + 8192, g_wlo + base);
        }
        CP_COMMIT();
    };

    float acc[2][4][4];
    uint32_t acch[2][4][2];
    #pragma unroll
    for (int mi = 0; mi < 2; mi++)
        #pragma unroll
        for (int ni = 0; ni < 4; ni++) {
            #pragma unroll
            for (int q = 0; q < 4; q++) acc[mi][ni][q] = 0.0f;
            acch[mi][ni][0] = 0u; acch[mi][ni][1] = 0u;
        }

    int arowb[2], arowx[2];
    #pragma unroll
    for (int mi = 0; mi < 2; mi++) {
        int r = warp_m * 32 + mi * 16 + (lane & 15);
        arowb[mi] = r * 128;
        arowx[mi] = r & 7;
    }
    int brow[2], browx[2];
    #pragma unroll
    for (int np = 0; np < 2; np++) {
        int n = warp_n * 32 + np * 16 + ((lane >> 4) << 3) + (lane & 7);
        brow[np]  = n * 128;
        browx[np] = n & 7;
    }
    const int asel = lane >> 4;
    const int bsel = (lane >> 3) & 1;

    load_chunk(0, 0);

    for (int k = 0; k < NCHX; k++) {
        const int p = k & 1;
        if (k + 1 < NCHX) load_chunk(k + 1, p ^ 1);
        if (k + 1 < NCHX) CP_WAIT(1); else CP_WAIT(0);
        __syncthreads();

        const uint32_t st = sbase + (p ? XST_BYTES : 0);
        #pragma unroll
        for (int kk = 0; kk < 4; kk++) {
            uint32_t ah[2][4], al[2][4];
            #pragma unroll
            for (int mi = 0; mi < 2; mi++) {
                int seg = 2 * kk + asel;
                uint32_t off = arowb[mi] + ((seg ^ arowx[mi]) << 4);
                LDSM_X4(ah[mi][0], ah[mi][1], ah[mi][2], ah[mi][3], st + off);
                LDSM_X4(al[mi][0], al[mi][1], al[mi][2], al[mi][3], st + XOFF_AL + off);
            }
            uint32_t bh[2][4], bl[2][4];
            #pragma unroll
            for (int np = 0; np < 2; np++) {
                int seg = 2 * kk + bsel;
                uint32_t off = brow[np] + ((seg ^ browx[np]) << 4);
                LDSM_X4(bh[np][0], bh[np][1], bh[np][2], bh[np][3], st + XOFF_BH + off);
                LDSM_X4(bl[np][0], bl[np][1], bl[np][2], bl[np][3], st + XOFF_BL + off);
            }
            #pragma unroll
            for (int mi = 0; mi < 2; mi++)
                #pragma unroll
                for (int np = 0; np < 2; np++)
                    #pragma unroll
                    for (int h = 0; h < 2; h++) {
                        int ni = np * 2 + h;
                        uint32_t bhf[2] = { bh[np][2 * h], bh[np][2 * h + 1] };
                        uint32_t blf[2] = { bl[np][2 * h], bl[np][2 * h + 1] };
                        MMA16816 (acc[mi][ni],  ah[mi], bhf);
                        MMA16816H(acch[mi][ni], ah[mi], blf);
                        MMA16816H(acch[mi][ni], al[mi], bhf);
                    }
        }
        __syncthreads();
    }

    float* xz = (seq < 2) ? g_xzA : g_xzB;
    const long zb = ((long)(seq & 1) * TN_ + t) * BN_;
    #pragma unroll
    for (int mi = 0; mi < 2; mi++) {
        #pragma unroll
        for (int ni = 0; ni < 4; ni++) {
            float2 c01 = __half22float2(*(__half2*)&acch[mi][ni][0]);
            float2 c23 = __half22float2(*(__half2*)&acch[mi][ni][1]);
            int col = n0 + warp_n * 32 + ni * 8 + 2 * (lane & 3);
            int r0  = b0 + warp_m * 32 + mi * 16 + (lane >> 2);
            float2 v01 = make_float2(acc[mi][ni][0] + c01.x, acc[mi][ni][1] + c01.y);
            float2 v23 = make_float2(acc[mi][ni][2] + c23.x, acc[mi][ni][3] + c23.y);
            *(float2*)&xz[(zb + r0)     * FOURH + col] = v01;
            *(float2*)&xz[(zb + r0 + 8) * FOURH + col] = v23;
        }
    }
}

// ---------------------------------------------------------------------------
// Per-step LSTM: z = xz[t] + h @ Wh  (K=512, 8 chunks). N-tile 64, 256
// threads = 8 warps (4m x 2n, warp tile 32x32). 2 CTAs resident per SM so
// prologue/epilogue/barrier phases of co-resident CTAs overlap.
#define ST_BYTES 49152
#define OFF_AL   16384
#define OFF_BH   32768
#define OFF_BL   40960
#define OFF_BIAS 98304
#define SMEM_TOTAL_STEP 98560

__global__ __launch_bounds__(256) void lstm_step_mma(const int* __restrict__ plen,
                                                     const int* __restrict__ hlen,
                                                     int s) {
    extern __shared__ char smem[];
    const uint32_t sbase = smem_u32(smem);
    const int tid  = threadIdx.x;
    const int lane = tid & 31;
    const int wid  = tid >> 5;
    const int warp_m = wid >> 1;       // 0..3 (32 rows each)
    const int warp_n = wid & 1;        // 0..1 (32 cols each)

    const int seq = blockIdx.z;
    const int rev = seq & 1;
    const int t   = rev ? (TN_ - 1 - s) : s;
    const int b0  = blockIdx.y * 128;
    const int n0  = blockIdx.x * 64;
    const int cur = s & 1;

    if (tid < 64)
        *(float*)(smem + OFF_BIAS + tid * 4) = g_bp[seq * FOURH + n0 + tid];

    const long hin_base  = ((long)cur * 4 + seq) * (BN_ * HN_);
    const long hout_base = ((long)(cur ^ 1) * 4 + seq) * (BN_ * HN_);

    auto load_chunk = [&](int k, int p) {
        const uint32_t st = sbase + (p ? ST_BYTES : 0);
        const int k0 = k * 64;
        #pragma unroll
        for (int j = 0; j < 4; j++) {           // A = h: 1024 segs, hi + lo
            int idx = tid + 256 * j;
            int row = idx >> 3;
            int seg = idx & 7;
            long base = hin_base + (long)(b0 + row) * HN_ + k0 + seg * 8;
            uint32_t dst = st + ((row * 8 + (seg ^ (row & 7))) << 4);
            cp16(dst,          g_hhi + base);
            cp16(dst + OFF_AL, g_hlo + base);
        }
        #pragma unroll
        for (int j = 0; j < 2; j++) {           // B = Wh region: 512 segs
            int idx = tid + 256 * j;
            int row = idx >> 3;
            int seg = idx & 7;
            long base = ((long)seq * FOURH + n0 + row) * KPAD + XPAD + k0 + seg * 8;
            uint32_t dst = st + OFF_BH + ((row * 8 + (seg ^ (row & 7))) << 4);
            cp16(dst,        g_whi + base);
            cp16(dst + 8192, g_wlo + base);
        }
        CP_COMMIT();
    };

    // acc init from precomputed xz
    float acc[2][4][4];
    uint32_t acch[2][4][2];
    {
        const float* xz = (seq < 2) ? g_xzA : g_xzB;
        const long zb = ((long)(seq & 1) * TN_ + t) * BN_;
        #pragma unroll
        for (int mi = 0; mi < 2; mi++)
            #pragma unroll
            for (int ni = 0; ni < 4; ni++) {
                int col = n0 + warp_n * 32 + ni * 8 + 2 * (lane & 3);
                int r0  = b0 + warp_m * 32 + mi * 16 + (lane >> 2);
                float2 v01 = *(const float2*)&xz[(zb + r0)     * FOURH + col];
                float2 v23 = *(const float2*)&xz[(zb + r0 + 8) * FOURH + col];
                acc[mi][ni][0] = v01.x; acc[mi][ni][1] = v01.y;
                acc[mi][ni][2] = v23.x; acc[mi][ni][3] = v23.y;
                acch[mi][ni][0] = 0u; acch[mi][ni][1] = 0u;
            }
    }

    int arowb[2], arowx[2];
    #pragma unroll
    for (int mi = 0; mi < 2; mi++) {
        int r = warp_m * 32 + mi * 16 + (lane & 15);
        arowb[mi] = r * 128;
        arowx[mi] = r & 7;
    }
    int brow[2], browx[2];
    #pragma unroll
    for (int np = 0; np < 2; np++) {
        int n = warp_n * 32 + np * 16 + ((lane >> 4) << 3) + (lane & 7);
        brow[np]  = n * 128;
        browx[np] = n & 7;
    }
    const int asel = lane >> 4;
    const int bsel = (lane >> 3) & 1;

    load_chunk(0, 0);

    for (int k = 0; k < NCHS; k++) {
        const int p = k & 1;
        if (k + 1 < NCHS) load_chunk(k + 1, p ^ 1);
        if (k + 1 < NCHS) CP_WAIT(1); else CP_WAIT(0);
        __syncthreads();

        const uint32_t st = sbase + (p ? ST_BYTES : 0);
        #pragma unroll
        for (int kk = 0; kk < 4; kk++) {
            uint32_t ah[2][4], al[2][4];
            #pragma unroll
            for (int mi = 0; mi < 2; mi++) {
                int seg = 2 * kk + asel;
                uint32_t off = arowb[mi] + ((seg ^ arowx[mi]) << 4);
                LDSM_X4(ah[mi][0], ah[mi][1], ah[mi][2], ah[mi][3], st + off);
                LDSM_X4(al[mi][0], al[mi][1], al[mi][2], al[mi][3], st + OFF_AL + off);
            }
            uint32_t bh[2][4], bl[2][4];
            #pragma unroll
            for (int np = 0; np < 2; np++) {
                int seg = 2 * kk + bsel;
                uint32_t off = brow[np] + ((seg ^ browx[np]) << 4);
                LDSM_X4(bh[np][0], bh[np][1], bh[np][2], bh[np][3], st + OFF_BH + off);
                LDSM_X4(bl[np][0], bl[np][1], bl[np][2], bl[np][3], st + OFF_BL + off);
            }
            #pragma unroll
            for (int mi = 0; mi < 2; mi++)
                #pragma unroll
                for (int np = 0; np < 2; np++)
                    #pragma unroll
                    for (int h = 0; h < 2; h++) {
                        int ni = np * 2 + h;
                        uint32_t bhf[2] = { bh[np][2 * h], bh[np][2 * h + 1] };
                        uint32_t blf[2] = { bl[np][2 * h], bl[np][2 * h + 1] };
                        MMA16816 (acc[mi][ni],  ah[mi], bhf);
                        MMA16816H(acch[mi][ni], ah[mi], blf);
                        MMA16816H(acch[mi][ni], al[mi], bhf);
                    }
        }
        __syncthreads();
    }

    // ---- epilogue: merge corrections, gates + masked state update ---------
    const int* __restrict__ len = (seq < 2) ? plen : hlen;
    const float* bias_s = (const float*)(smem + OFF_BIAS);
    const bool amain = ((lane & 1) == 0);

    #pragma unroll
    for (int mi = 0; mi < 2; mi++) {
        #pragma unroll
        for (int ni = 0; ni < 4; ni++) {
            float2 c01 = __half22float2(*(__half2*)&acch[mi][ni][0]);
            float2 c23 = __half22float2(*(__half2*)&acch[mi][ni][1]);
            int col_local = warp_n * 32 + ni * 8 + 2 * (lane & 3);
            float v0 = acc[mi][ni][0] + c01.x + bias_s[col_local];
            float v1 = acc[mi][ni][1] + c01.y + bias_s[col_local + 1];
            float v2 = acc[mi][ni][2] + c23.x + bias_s[col_local];
            float v3 = acc[mi][ni][3] + c23.y + bias_s[col_local + 1];
            float p0 = __shfl_xor_sync(0xffffffffu, v0, 1);
            float p1 = __shfl_xor_sync(0xffffffffu, v1, 1);
            float p2 = __shfl_xor_sync(0xffffffffu, v2, 1);
            float p3 = __shfl_xor_sync(0xffffffffu, v3, 1);
            if (amain) {
                int u = (n0 + col_local) >> 2;
                #pragma unroll
                for (int rh = 0; rh < 2; rh++) {
                    int b = b0 + warp_m * 32 + mi * 16 + (lane >> 2) + rh * 8;
                    float iv = rh ? v2 : v0;
                    float jv = rh ? v3 : v1;
                    float fv = rh ? p2 : p0;
                    float ov = rh ? p3 : p1;
                    bool m = (t < len[b]);
                    long hidx = (long)b * HN_ + u;
                    float c_old = g_c[seq][b][u];
                    float nc = c_old * sigmoidf_(fv + 1.0f) + sigmoidf_(iv) * tanhf(jv);
                    float nh = tanhf(nc) * sigmoidf_(ov);
                    g_c[seq][b][u] = m ? nc : c_old;
                    __half hh, hl;
                    if (m) {
                        hh = __float2half(nh);
                        hl = __float2half(nh - __half2float(hh));
                    } else {
                        hh = g_hhi[hin_base + hidx];
                        hl = g_hlo[hin_base + hidx];
                    }
                    g_hhi[hout_base + hidx] = hh;
                    g_hlo[hout_base + hidx] = hl;
                }
            }
        }
    }
}

// ---------------------------------------------------------------------------
// MLP head (fp32)
__global__ void gather_x_kernel() {
    int i = blockIdx.x * blockDim.x + threadIdx.x;
    if (i >= BN_ * FOURH) return;
    int b   = i >> 11;
    int col = i & 2047;
    g_x[i] = g_c[col >> 9][b][col & 511];
}

#define BMT 64
#define BUT 64
#define KT  16
__global__ __launch_bounds__(256) void mlp_gemm_kernel(const float* __restrict__ W,
                                                       const float* __restrict__ bias,
                                                       int layer) {
    const float* A; float* C; int K, N;
    if (layer == 1)      { A = g_x;  C = g_m1; K = 2048; N = 1024; }
    else if (layer == 2) { A = g_m1; C = g_m2; K = 1024; N = 1024; }
    else                 { A = g_m2; C = g_m3; K = 1024; N = 1024; }

    const int m0 = blockIdx.y * BMT;
    const int n0 = blockIdx.x * BUT;
    __shared__ float As[KT][BMT];
    __shared__ float Bs[KT][BUT];
    const int tid = threadIdx.x;
    const int r0  = (tid >> 4) * 4;
    const int nt0 = (tid & 15) * 4;

    float acc[4][4];
    #pragma unroll
    for (int r = 0; r < 4; r++)
        #pragma unroll
        for (int u = 0; u < 4; u++) acc[r][u] = 0.0f;

    for (int k0 = 0; k0 < K; k0 += KT) {
        {
            int r  = tid >> 2;
            int kq = (tid & 3) * 4;
            #pragma unroll
            for (int i = 0; i < 4; i++)
                As[kq + i][r] = A[(m0 + r) * K + k0 + kq + i];
        }
        {
            int kk = tid >> 4;
            int uu = (tid & 15) * 4;
            *(float4*)&Bs[kk][uu] = *(const float4*)(W + (k0 + kk) * N + n0 + uu);
        }
        __syncthreads();
        #pragma unroll
        for (int kk = 0; kk < KT; kk++) {
            float4 a4 = *(const float4*)&As[kk][r0];
            float4 b4 = *(const float4*)&Bs[kk][nt0];
            float av[4] = {a4.x, a4.y, a4.z, a4.w};
            float bv[4] = {b4.x, b4.y, b4.z, b4.w};
            #pragma unroll
            for (int r = 0; r < 4; r++)
                #pragma unroll
                for (int u = 0; u < 4; u++)
                    acc[r][u] = fmaf(av[r], bv[u], acc[r][u]);
        }
        __syncthreads();
    }
    #pragma unroll
    for (int r = 0; r < 4; r++)
        #pragma unroll
        for (int u = 0; u < 4; u++) {
            int n = n0 + nt0 + u;
            C[(m0 + r0 + r) * N + n] = tanhf(acc[r][u] + bias[n]);
        }
}

__global__ void final_logits_kernel(const float* __restrict__ W4,
                                    const float* __restrict__ b4,
                                    float* __restrict__ out) {
    int b    = blockIdx.x;
    int w    = threadIdx.x >> 5;
    int lane = threadIdx.x & 31;
    if (w >= 3) return;
    float sum = 0.0f;
    for (int k = lane; k < 1024; k += 32)
        sum += g_m3[b * 1024 + k] * W4[k * 3 + w];
    #pragma unroll
    for (int off = 16; off; off >>= 1)
        sum += __shfl_down_sync(0xffffffff, sum, off);
    if (lane == 0) out[b * 3 + w] = sum + b4[w];
}

// ---------------------------------------------------------------------------
extern "C" void kernel_launch(void* const* d_in, const int* in_sizes, int n_in,
                              void* d_out, int out_size) {
    const float* premises   = (const float*)d_in[0];
    const float* hypotheses = (const float*)d_in[1];
    const int*   plen       = (const int*)d_in[2];
    const int*   hlen       = (const int*)d_in[3];

    WPtrs wp;
    for (int i = 0; i < 4; i++) {
        wp.wx[i]   = (const float*)d_in[4 + 3 * i + 0];
        wp.wh[i]   = (const float*)d_in[4 + 3 * i + 1];
        wp.bias[i] = (const float*)d_in[4 + 3 * i + 2];
    }
    const float* W1 = (const float*)d_in[16];
    const float* b1 = (const float*)d_in[17];
    const float* W2 = (const float*)d_in[18];
    const float* b2 = (const float*)d_in[19];
    const float* W3 = (const float*)d_in[20];
    const float* b3 = (const float*)d_in[21];
    const float* W4 = (const float*)d_in[22];
    const float* b4 = (const float*)d_in[23];
    float* out = (float*)d_out;

    cudaFuncSetAttribute(lstm_step_mma, cudaFuncAttributeMaxDynamicSharedMemorySize,
                         SMEM_TOTAL_STEP);
    cudaFuncSetAttribute(xz_gemm, cudaFuncAttributeMaxDynamicSharedMemorySize,
                         SMEM_XZ);

    // 1) preprocessing (one launch)
    {
        long long n = NTOT_;
        preproc_all<<<(unsigned)((n + 255) / 256), 256>>>(premises, hypotheses, wp);
    }

    // 2) xz = x @ Wx for all seqs/timesteps (one big parallel GEMM)
    xz_gemm<<<dim3(32, 2, 4 * TN_), 256, SMEM_XZ>>>();

    // 3) recurrence over h only (K=512), 256 CTAs -> 2 per SM
    dim3 grid(32, 2, 4);
    for (int s = 0; s < TN_; s++)
        lstm_step_mma<<<grid, 256, SMEM_TOTAL_STEP>>>(plen, hlen, s);

    // 4) MLP head
    gather_x_kernel<<<(BN_ * FOURH + 255) / 256, 256>>>();
    mlp_gemm_kernel<<<dim3(1024 / BUT, BN_ / BMT), 256>>>(W1, b1, 1);
    mlp_gemm_kernel<<<dim3(1024 / BUT, BN_ / BMT), 256>>>(W2, b2, 2);
    mlp_gemm_kernel<<<dim3(1024 / BUT, BN_ / BMT), 256>>>(W3, b3, 3);
    final_logits_kernel<<<BN_, 96>>>(W4, b4, out);
}

// round 9
// speedup vs baseline: 1.0557x; 1.0557x over previous
#include <cuda_runtime.h>
#include <cuda_fp16.h>
#include <math.h>
#include <stdint.h>

// ---------------------------------------------------------------------------
// Problem constants
#define BN_   256   // batch
#define TN_   256   // time steps
#define DN_   300   // input dim
#define HN_   512   // hidden
#define XPAD  320   // x padded to 320 (5 chunks of 64)
#define KPAD  832   // 320 + 512 (W layout rows)
#define NCHX  5     // x chunks (precompute GEMM)
#define NCHS  8     // h chunks (per-step GEMM, K=512)
#define FOURH 2048

// ---------------------------------------------------------------------------
// Scratch (device globals)
__device__ __half g_xhi[2ll * BN_ * TN_ * XPAD];
__device__ __half g_xlo[2ll * BN_ * TN_ * XPAD];
__device__ __half g_whi[4ll * FOURH * KPAD];
__device__ __half g_wlo[4ll * FOURH * KPAD];
__device__ float  g_bp [4 * FOURH];                 // permuted bias
__device__ __half g_hhi[2ll * 4 * BN_ * HN_];       // double-buffered h hi
__device__ __half g_hlo[2ll * 4 * BN_ * HN_];       // double-buffered h lo
__device__ float  g_c  [4][BN_][HN_];               // cell state
__device__ float  g_x  [BN_ * FOURH];               // concat c -> MLP input
__device__ float  g_m1[BN_ * 1024];
__device__ float  g_m2[BN_ * 1024];
__device__ float  g_m3[BN_ * 1024];

// Precomputed x-projections: xz[seqpair][t][b][n], fp32 (two 1 GiB arrays)
#define XZ_PER (2ll * TN_ * BN_ * FOURH)
__device__ float g_xzA[XZ_PER];
__device__ float g_xzB[XZ_PER];

__device__ __forceinline__ float sigmoidf_(float v) { return 1.0f / (1.0f + expf(-v)); }

__device__ __forceinline__ uint32_t smem_u32(const void* p) {
    uint32_t a;
    asm("{ .reg .u64 t; cvta.to.shared.u64 t, %1; cvt.u32.u64 %0, t; }" : "=r"(a) : "l"(p));
    return a;
}
__device__ __forceinline__ void cp16(uint32_t dst, const void* src) {
    asm volatile("cp.async.cg.shared.global [%0], [%1], 16;" :: "r"(dst), "l"(src));
}
#define CP_COMMIT() asm volatile("cp.async.commit_group;" ::: "memory")
#define CP_WAIT(N)  asm volatile("cp.async.wait_group %0;" :: "n"(N) : "memory")

#define LDSM_X4(r0, r1, r2, r3, addr)                                         \
    asm volatile("ldmatrix.sync.aligned.m8n8.x4.shared.b16 {%0,%1,%2,%3}, [%4];" \
        : "=r"(r0), "=r"(r1), "=r"(r2), "=r"(r3) : "r"(addr))

// f32-accumulate HMMA (main product)
#define MMA16816(d, a, b)                                                     \
    asm volatile("mma.sync.aligned.m16n8k16.row.col.f32.f16.f16.f32 "         \
        "{%0,%1,%2,%3}, {%4,%5,%6,%7}, {%8,%9}, {%0,%1,%2,%3};"               \
        : "+f"((d)[0]), "+f"((d)[1]), "+f"((d)[2]), "+f"((d)[3])              \
        : "r"((a)[0]), "r"((a)[1]), "r"((a)[2]), "r"((a)[3]),                 \
          "r"((b)[0]), "r"((b)[1]))

// f16-accumulate HMMA (correction products)
#define MMA16816H(d, a, b)                                                    \
    asm volatile("mma.sync.aligned.m16n8k16.row.col.f16.f16.f16.f16 "         \
        "{%0,%1}, {%2,%3,%4,%5}, {%6,%7}, {%0,%1};"                           \
        : "+r"((d)[0]), "+r"((d)[1])                                          \
        : "r"((a)[0]), "r"((a)[1]), "r"((a)[2]), "r"((a)[3]),                 \
          "r"((b)[0]), "r"((b)[1]))

// ---------------------------------------------------------------------------
// Fused one-shot preprocessing (single launch)
struct WPtrs { const float* wx[4]; const float* wh[4]; const float* bias[4]; };

#define NXE_ (2ll * BN_ * TN_ * XPAD)
#define NWE_ (4ll * FOURH * KPAD)
#define NHE_ (2ll * 4 * BN_ * HN_)
#define NCE_ (4ll * BN_ * HN_)
#define NBE_ (4ll * FOURH)
#define NTOT_ (NXE_ + NWE_ + NHE_ + NCE_ + NBE_)

__global__ void preproc_all(const float* __restrict__ prem, const float* __restrict__ hyp,
                            WPtrs wp) {
    long long i = (long long)blockIdx.x * blockDim.x + threadIdx.x;
    if (i < NXE_) {
        int k = (int)(i % XPAD);
        long long r = i / XPAD;
        int t = (int)(r % TN_); r /= TN_;
        int b = (int)(r % BN_);
        int inp = (int)(r / BN_);
        float v = 0.0f;
        if (k < DN_) {
            const float* src = inp ? hyp : prem;
            v = src[((long long)b * TN_ + t) * DN_ + k];
        }
        __half h = __float2half(v);
        g_xhi[i] = h;
        g_xlo[i] = __float2half(v - __half2float(h));
        return;
    }
    i -= NXE_;
    if (i < NWE_) {
        int kp = (int)(i % KPAD);
        long long r = i / KPAD;
        int c   = (int)(r % FOURH);
        int seq = (int)(r / FOURH);
        int oc  = (c & 3) * HN_ + (c >> 2);          // gate-interleaved col' = u*4+g
        float v = 0.0f;
        if (kp < DN_)        v = wp.wx[seq][(long long)kp * FOURH + oc];
        else if (kp >= XPAD) v = wp.wh[seq][(long long)(kp - XPAD) * FOURH + oc];
        __half h = __float2half(v);
        g_whi[i] = h;
        g_wlo[i] = __float2half(v - __half2float(h));
        return;
    }
    i -= NWE_;
    if (i < NHE_) {
        g_hhi[i] = __float2half(0.f);
        g_hlo[i] = __float2half(0.f);
        return;
    }
    i -= NHE_;
    if (i < NCE_) {
        (&g_c[0][0][0])[i] = 0.0f;
        return;
    }
    i -= NCE_;
    if (i < NBE_) {
        int c = (int)(i & (FOURH - 1));
        int seq = (int)(i >> 11);
        g_bp[i] = wp.bias[seq][(c & 3) * HN_ + (c >> 2)];
    }
}

// ---------------------------------------------------------------------------
// xz precompute GEMM: xz[seq][t][b][n] = x[b,t,:] @ Wx_seq (fp16 hi/lo split).
// Tile 128(b) x 64(n), 256 threads = 8 warps (4m x 2n), warp tile 32x32.
#define XST_BYTES 49152
#define XOFF_AL   16384
#define XOFF_BH   32768
#define XOFF_BL   40960
#define SMEM_XZ   98304

__global__ __launch_bounds__(256) void xz_gemm() {
    extern __shared__ char smem[];
    const uint32_t sbase = smem_u32(smem);
    const int tid  = threadIdx.x;
    const int lane = tid & 31;
    const int wid  = tid >> 5;
    const int warp_m = wid >> 1;       // 0..3
    const int warp_n = wid & 1;        // 0..1

    const int z   = blockIdx.z;        // seq*TN_ + t
    const int seq = z >> 8;
    const int t   = z & 255;
    const int inp = seq >> 1;
    const int b0  = blockIdx.y * 128;
    const int n0  = blockIdx.x * 64;

    auto load_chunk = [&](int k, int p) {
        const uint32_t st = sbase + (p ? XST_BYTES : 0);
        const int k0 = k * 64;
        #pragma unroll
        for (int j = 0; j < 4; j++) {           // A: 1024 segs, hi + lo
            int idx = tid + 256 * j;
            int row = idx >> 3;
            int seg = idx & 7;
            long base = ((long)(inp * BN_ + b0 + row) * TN_ + t) * XPAD + k0 + seg * 8;
            uint32_t dst = st + ((row * 8 + (seg ^ (row & 7))) << 4);
            cp16(dst,           g_xhi + base);
            cp16(dst + XOFF_AL, g_xlo + base);
        }
        #pragma unroll
        for (int j = 0; j < 2; j++) {           // B: 512 segs, hi + lo
            int idx = tid + 256 * j;
            int row = idx >> 3;
            int seg = idx & 7;
            long base = ((long)seq * FOURH + n0 + row) * KPAD + k0 + seg * 8;
            uint32_t dst = st + XOFF_BH + ((row * 8 + (seg ^ (row & 7))) << 4);
            cp16(dst,        g_whi + base);
            cp16(dst + 8192, g_wlo + base);
        }
        CP_COMMIT();
    };

    float acc[2][4][4];
    uint32_t acch[2][4][2];
    #pragma unroll
    for (int mi = 0; mi < 2; mi++)
        #pragma unroll
        for (int ni = 0; ni < 4; ni++) {
            #pragma unroll
            for (int q = 0; q < 4; q++) acc[mi][ni][q] = 0.0f;
            acch[mi][ni][0] = 0u; acch[mi][ni][1] = 0u;
        }

    int arowb[2], arowx[2];
    #pragma unroll
    for (int mi = 0; mi < 2; mi++) {
        int r = warp_m * 32 + mi * 16 + (lane & 15);
        arowb[mi] = r * 128;
        arowx[mi] = r & 7;
    }
    int brow[2], browx[2];
    #pragma unroll
    for (int np = 0; np < 2; np++) {
        int n = warp_n * 32 + np * 16 + ((lane >> 4) << 3) + (lane & 7);
        brow[np]  = n * 128;
        browx[np] = n & 7;
    }
    const int asel = lane >> 4;
    const int bsel = (lane >> 3) & 1;

    load_chunk(0, 0);

    for (int k = 0; k < NCHX; k++) {
        const int p = k & 1;
        if (k + 1 < NCHX) load_chunk(k + 1, p ^ 1);
        if (k + 1 < NCHX) CP_WAIT(1); else CP_WAIT(0);
        __syncthreads();

        const uint32_t st = sbase + (p ? XST_BYTES : 0);
        #pragma unroll
        for (int kk = 0; kk < 4; kk++) {
            uint32_t ah[2][4], al[2][4];
            #pragma unroll
            for (int mi = 0; mi < 2; mi++) {
                int seg = 2 * kk + asel;
                uint32_t off = arowb[mi] + ((seg ^ arowx[mi]) << 4);
                LDSM_X4(ah[mi][0], ah[mi][1], ah[mi][2], ah[mi][3], st + off);
                LDSM_X4(al[mi][0], al[mi][1], al[mi][2], al[mi][3], st + XOFF_AL + off);
            }
            uint32_t bh[2][4], bl[2][4];
            #pragma unroll
            for (int np = 0; np < 2; np++) {
                int seg = 2 * kk + bsel;
                uint32_t off = brow[np] + ((seg ^ browx[np]) << 4);
                LDSM_X4(bh[np][0], bh[np][1], bh[np][2], bh[np][3], st + XOFF_BH + off);
                LDSM_X4(bl[np][0], bl[np][1], bl[np][2], bl[np][3], st + XOFF_BL + off);
            }
            #pragma unroll
            for (int mi = 0; mi < 2; mi++)
                #pragma unroll
                for (int np = 0; np < 2; np++)
                    #pragma unroll
                    for (int h = 0; h < 2; h++) {
                        int ni = np * 2 + h;
                        uint32_t bhf[2] = { bh[np][2 * h], bh[np][2 * h + 1] };
                        uint32_t blf[2] = { bl[np][2 * h], bl[np][2 * h + 1] };
                        MMA16816 (acc[mi][ni],  ah[mi], bhf);
                        MMA16816H(acch[mi][ni], ah[mi], blf);
                        MMA16816H(acch[mi][ni], al[mi], bhf);
                    }
        }
        __syncthreads();
    }

    float* xz = (seq < 2) ? g_xzA : g_xzB;
    const long zb = ((long)(seq & 1) * TN_ + t) * BN_;
    #pragma unroll
    for (int mi = 0; mi < 2; mi++) {
        #pragma unroll
        for (int ni = 0; ni < 4; ni++) {
            float2 c01 = __half22float2(*(__half2*)&acch[mi][ni][0]);
            float2 c23 = __half22float2(*(__half2*)&acch[mi][ni][1]);
            int col = n0 + warp_n * 32 + ni * 8 + 2 * (lane & 3);
            int r0  = b0 + warp_m * 32 + mi * 16 + (lane >> 2);
            float2 v01 = make_float2(acc[mi][ni][0] + c01.x, acc[mi][ni][1] + c01.y);
            float2 v23 = make_float2(acc[mi][ni][2] + c23.x, acc[mi][ni][3] + c23.y);
            *(float2*)&xz[(zb + r0)     * FOURH + col] = v01;
            *(float2*)&xz[(zb + r0 + 8) * FOURH + col] = v23;
        }
    }
}

// ---------------------------------------------------------------------------
// Per-step LSTM: z = xz[t] + h @ Wh  (K=512, 8 chunks). 512 threads, 16 warps
// (4m x 4n), warp tile 32x32. xz and c are streamed into SMEM via cp.async
// spread across the chunk loop and consumed only in the epilogue, so the
// per-step DRAM burst overlaps the MMA phase instead of stalling the start.
#define ST_BYTES 65536
#define OFF_AL   16384
#define OFF_BH   32768
#define OFF_BL   49152
#define OFF_XZ   131072      // 64 KB: xz block [128 rows][128 cols] fp32
#define OFF_C    196608      // 16 KB: c block  [128 rows][32 units] fp32
#define OFF_BIAS 212992      // 512 B
#define SMEM_TOTAL_STEP 213504

__global__ __launch_bounds__(512) void lstm_step_mma(const int* __restrict__ plen,
                                                     const int* __restrict__ hlen,
                                                     int s) {
    extern __shared__ char smem[];
    const uint32_t sbase = smem_u32(smem);
    const int tid  = threadIdx.x;
    const int lane = tid & 31;
    const int wid  = tid >> 5;
    const int warp_m = wid >> 2;       // 0..3
    const int warp_n = wid & 3;        // 0..3

    const int seq = blockIdx.z;
    const int rev = seq & 1;
    const int t   = rev ? (TN_ - 1 - s) : s;
    const int b0  = blockIdx.y * 128;
    const int n0  = blockIdx.x * 128;
    const int u0  = n0 >> 2;           // 32 units per tile
    const int cur = s & 1;

    if (tid < 128)
        *(float*)(smem + OFF_BIAS + tid * 4) = g_bp[seq * FOURH + n0 + tid];

    const long hin_base  = ((long)cur * 4 + seq) * (BN_ * HN_);
    const long hout_base = ((long)(cur ^ 1) * 4 + seq) * (BN_ * HN_);
    const float* __restrict__ xzg = (seq < 2) ? g_xzA : g_xzB;
    const long zb = ((long)(seq & 1) * TN_ + t) * BN_;

    auto load_chunk = [&](int k, int p) {
        const uint32_t st = sbase + (p ? ST_BYTES : 0);
        const int k0 = k * 64;
        #pragma unroll
        for (int j = 0; j < 2; j++) {           // A = h: hi + lo
            int idx = tid + 512 * j;
            int row = idx >> 3;
            int seg = idx & 7;
            long base = hin_base + (long)(b0 + row) * HN_ + k0 + seg * 8;
            uint32_t dst = st + ((row * 8 + (seg ^ (row & 7))) << 4);
            cp16(dst,          g_hhi + base);
            cp16(dst + OFF_AL, g_hlo + base);
        }
        #pragma unroll
        for (int j = 0; j < 2; j++) {           // B = Wh region: hi + lo
            int idx = tid + 512 * j;
            int row = idx >> 3;
            int seg = idx & 7;
            long base = ((long)seq * FOURH + n0 + row) * KPAD + XPAD + k0 + seg * 8;
            uint32_t dst = st + OFF_BH + ((row * 8 + (seg ^ (row & 7))) << 4);
            cp16(dst,         g_whi + base);
            cp16(dst + 16384, g_wlo + base);
        }
        // xz piece k: 16 rows x 128 cols fp32 = 512 x 16B segs (1/thread)
        {
            int row = (k << 4) + (tid >> 5);
            int seg = tid & 31;
            const float* src = xzg + (zb + b0 + row) * FOURH + n0 + seg * 4;
            cp16(sbase + OFF_XZ + row * 512 + seg * 16, src);
        }
        // c piece k: 16 rows x 32 units fp32 = 128 x 16B segs
        if (tid < 128) {
            int row = (k << 4) + (tid >> 3);
            int seg = tid & 7;
            const float* src = &g_c[seq][b0 + row][u0 + seg * 4];
            cp16(sbase + OFF_C + row * 128 + seg * 16, src);
        }
        CP_COMMIT();
    };

    // accumulators start at zero; xz added in epilogue
    float acc[2][4][4];
    uint32_t acch[2][4][2];
    #pragma unroll
    for (int mi = 0; mi < 2; mi++)
        #pragma unroll
        for (int ni = 0; ni < 4; ni++) {
            #pragma unroll
            for (int q = 0; q < 4; q++) acc[mi][ni][q] = 0.0f;
            acch[mi][ni][0] = 0u; acch[mi][ni][1] = 0u;
        }

    int arowb[2], arowx[2];
    #pragma unroll
    for (int mi = 0; mi < 2; mi++) {
        int r = warp_m * 32 + mi * 16 + (lane & 15);
        arowb[mi] = r * 128;
        arowx[mi] = r & 7;
    }
    int brow[2], browx[2];
    #pragma unroll
    for (int np = 0; np < 2; np++) {
        int n = warp_n * 32 + np * 16 + ((lane >> 4) << 3) + (lane & 7);
        brow[np]  = n * 128;
        browx[np] = n & 7;
    }
    const int asel = lane >> 4;
    const int bsel = (lane >> 3) & 1;

    load_chunk(0, 0);

    for (int k = 0; k < NCHS; k++) {
        const int p = k & 1;
        if (k + 1 < NCHS) load_chunk(k + 1, p ^ 1);
        if (k + 1 < NCHS) CP_WAIT(1); else CP_WAIT(0);
        __syncthreads();

        const uint32_t st = sbase + (p ? ST_BYTES : 0);
        #pragma unroll
        for (int kk = 0; kk < 4; kk++) {
            uint32_t ah[2][4], al[2][4];
            #pragma unroll
            for (int mi = 0; mi < 2; mi++) {
                int seg = 2 * kk + asel;
                uint32_t off = arowb[mi] + ((seg ^ arowx[mi]) << 4);
                LDSM_X4(ah[mi][0], ah[mi][1], ah[mi][2], ah[mi][3], st + off);
                LDSM_X4(al[mi][0], al[mi][1], al[mi][2], al[mi][3], st + OFF_AL + off);
            }
            uint32_t bh[2][4], bl[2][4];
            #pragma unroll
            for (int np = 0; np < 2; np++) {
                int seg = 2 * kk + bsel;
                uint32_t off = brow[np] + ((seg ^ browx[np]) << 4);
                LDSM_X4(bh[np][0], bh[np][1], bh[np][2], bh[np][3], st + OFF_BH + off);
                LDSM_X4(bl[np][0], bl[np][1], bl[np][2], bl[np][3], st + OFF_BL + off);
            }
            #pragma unroll
            for (int mi = 0; mi < 2; mi++)
                #pragma unroll
                for (int np = 0; np < 2; np++)
                    #pragma unroll
                    for (int h = 0; h < 2; h++) {
                        int ni = np * 2 + h;
                        uint32_t bhf[2] = { bh[np][2 * h], bh[np][2 * h + 1] };
                        uint32_t blf[2] = { bl[np][2 * h], bl[np][2 * h + 1] };
                        MMA16816 (acc[mi][ni],  ah[mi], bhf);
                        MMA16816H(acch[mi][ni], ah[mi], blf);
                        MMA16816H(acch[mi][ni], al[mi], bhf);
                    }
        }
        __syncthreads();
    }

    // ---- epilogue: + xz (smem) + bias, gates, masked state update ---------
    const int* __restrict__ len = (seq < 2) ? plen : hlen;
    const float* bias_s = (const float*)(smem + OFF_BIAS);
    const float* xz_s   = (const float*)(smem + OFF_XZ);   // [row][128 cols]
    const float* c_s    = (const float*)(smem + OFF_C);    // [row][32 units]
    const bool amain = ((lane & 1) == 0);

    #pragma unroll
    for (int mi = 0; mi < 2; mi++) {
        #pragma unroll
        for (int ni = 0; ni < 4; ni++) {
            float2 c01 = __half22float2(*(__half2*)&acch[mi][ni][0]);
            float2 c23 = __half22float2(*(__half2*)&acch[mi][ni][1]);
            int col_local = warp_n * 32 + ni * 8 + 2 * (lane & 3);
            int rl0 = warp_m * 32 + mi * 16 + (lane >> 2);
            float2 x01 = *(const float2*)&xz_s[rl0 * 128 + col_local];
            float2 x23 = *(const float2*)&xz_s[(rl0 + 8) * 128 + col_local];
            float v0 = acc[mi][ni][0] + c01.x + x01.x + bias_s[col_local];
            float v1 = acc[mi][ni][1] + c01.y + x01.y + bias_s[col_local + 1];
            float v2 = acc[mi][ni][2] + c23.x + x23.x + bias_s[col_local];
            float v3 = acc[mi][ni][3] + c23.y + x23.y + bias_s[col_local + 1];
            float p0 = __shfl_xor_sync(0xffffffffu, v0, 1);
            float p1 = __shfl_xor_sync(0xffffffffu, v1, 1);
            float p2 = __shfl_xor_sync(0xffffffffu, v2, 1);
            float p3 = __shfl_xor_sync(0xffffffffu, v3, 1);
            if (amain) {
                int u_local = col_local >> 2;
                int u = u0 + u_local;
                #pragma unroll
                for (int rh = 0; rh < 2; rh++) {
                    int rl = rl0 + rh * 8;
                    int b  = b0 + rl;
                    float iv = rh ? v2 : v0;
                    float jv = rh ? v3 : v1;
                    float fv = rh ? p2 : p0;
                    float ov = rh ? p3 : p1;
                    bool m = (t < len[b]);
                    long hidx = (long)b * HN_ + u;
                    float c_old = c_s[rl * 32 + u_local];
                    float nc = c_old * sigmoidf_(fv + 1.0f) + sigmoidf_(iv) * tanhf(jv);
                    float nh = tanhf(nc) * sigmoidf_(ov);
                    g_c[seq][b][u] = m ? nc : c_old;
                    __half hh, hl;
                    if (m) {
                        hh = __float2half(nh);
                        hl = __float2half(nh - __half2float(hh));
                    } else {
                        hh = g_hhi[hin_base + hidx];
                        hl = g_hlo[hin_base + hidx];
                    }
                    g_hhi[hout_base + hidx] = hh;
                    g_hlo[hout_base + hidx] = hl;
                }
            }
        }
    }
}

// ---------------------------------------------------------------------------
// MLP head (fp32)
__global__ void gather_x_kernel() {
    int i = blockIdx.x * blockDim.x + threadIdx.x;
    if (i >= BN_ * FOURH) return;
    int b   = i >> 11;
    int col = i & 2047;
    g_x[i] = g_c[col >> 9][b][col & 511];
}

#define BMT 64
#define BUT 64
#define KT  16
__global__ __launch_bounds__(256) void mlp_gemm_kernel(const float* __restrict__ W,
                                                       const float* __restrict__ bias,
                                                       int layer) {
    const float* A; float* C; int K, N;
    if (layer == 1)      { A = g_x;  C = g_m1; K = 2048; N = 1024; }
    else if (layer == 2) { A = g_m1; C = g_m2; K = 1024; N = 1024; }
    else                 { A = g_m2; C = g_m3; K = 1024; N = 1024; }

    const int m0 = blockIdx.y * BMT;
    const int n0 = blockIdx.x * BUT;
    __shared__ float As[KT][BMT];
    __shared__ float Bs[KT][BUT];
    const int tid = threadIdx.x;
    const int r0  = (tid >> 4) * 4;
    const int nt0 = (tid & 15) * 4;

    float acc[4][4];
    #pragma unroll
    for (int r = 0; r < 4; r++)
        #pragma unroll
        for (int u = 0; u < 4; u++) acc[r][u] = 0.0f;

    for (int k0 = 0; k0 < K; k0 += KT) {
        {
            int r  = tid >> 2;
            int kq = (tid & 3) * 4;
            #pragma unroll
            for (int i = 0; i < 4; i++)
                As[kq + i][r] = A[(m0 + r) * K + k0 + kq + i];
        }
        {
            int kk = tid >> 4;
            int uu = (tid & 15) * 4;
            *(float4*)&Bs[kk][uu] = *(const float4*)(W + (k0 + kk) * N + n0 + uu);
        }
        __syncthreads();
        #pragma unroll
        for (int kk = 0; kk < KT; kk++) {
            float4 a4 = *(const float4*)&As[kk][r0];
            float4 b4 = *(const float4*)&Bs[kk][nt0];
            float av[4] = {a4.x, a4.y, a4.z, a4.w};
            float bv[4] = {b4.x, b4.y, b4.z, b4.w};
            #pragma unroll
            for (int r = 0; r < 4; r++)
                #pragma unroll
                for (int u = 0; u < 4; u++)
                    acc[r][u] = fmaf(av[r], bv[u], acc[r][u]);
        }
        __syncthreads();
    }
    #pragma unroll
    for (int r = 0; r < 4; r++)
        #pragma unroll
        for (int u = 0; u < 4; u++) {
            int n = n0 + nt0 + u;
            C[(m0 + r0 + r) * N + n] = tanhf(acc[r][u] + bias[n]);
        }
}

__global__ void final_logits_kernel(const float* __restrict__ W4,
                                    const float* __restrict__ b4,
                                    float* __restrict__ out) {
    int b    = blockIdx.x;
    int w    = threadIdx.x >> 5;
    int lane = threadIdx.x & 31;
    if (w >= 3) return;
    float sum = 0.0f;
    for (int k = lane; k < 1024; k += 32)
        sum += g_m3[b * 1024 + k] * W4[k * 3 + w];
    #pragma unroll
    for (int off = 16; off; off >>= 1)
        sum += __shfl_down_sync(0xffffffff, sum, off);
    if (lane == 0) out[b * 3 + w] = sum + b4[w];
}

// ---------------------------------------------------------------------------
extern "C" void kernel_launch(void* const* d_in, const int* in_sizes, int n_in,
                              void* d_out, int out_size) {
    const float* premises   = (const float*)d_in[0];
    const float* hypotheses = (const float*)d_in[1];
    const int*   plen       = (const int*)d_in[2];
    const int*   hlen       = (const int*)d_in[3];

    WPtrs wp;
    for (int i = 0; i < 4; i++) {
        wp.wx[i]   = (const float*)d_in[4 + 3 * i + 0];
        wp.wh[i]   = (const float*)d_in[4 + 3 * i + 1];
        wp.bias[i] = (const float*)d_in[4 + 3 * i + 2];
    }
    const float* W1 = (const float*)d_in[16];
    const float* b1 = (const float*)d_in[17];
    const float* W2 = (const float*)d_in[18];
    const float* b2 = (const float*)d_in[19];
    const float* W3 = (const float*)d_in[20];
    const float* b3 = (const float*)d_in[21];
    const float* W4 = (const float*)d_in[22];
    const float* b4 = (const float*)d_in[23];
    float* out = (float*)d_out;

    cudaFuncSetAttribute(lstm_step_mma, cudaFuncAttributeMaxDynamicSharedMemorySize,
                         SMEM_TOTAL_STEP);
    cudaFuncSetAttribute(xz_gemm, cudaFuncAttributeMaxDynamicSharedMemorySize,
                         SMEM_XZ);

    // 1) preprocessing (one launch)
    {
        long long n = NTOT_;
        preproc_all<<<(unsigned)((n + 255) / 256), 256>>>(premises, hypotheses, wp);
    }

    // 2) xz = x @ Wx for all seqs/timesteps (one big parallel GEMM)
    xz_gemm<<<dim3(32, 2, 4 * TN_), 256, SMEM_XZ>>>();

    // 3) recurrence over h only (K=512), 128 CTAs, 512 threads
    dim3 grid(16, 2, 4);
    for (int s = 0; s < TN_; s++)
        lstm_step_mma<<<grid, 512, SMEM_TOTAL_STEP>>>(plen, hlen, s);

    // 4) MLP head
    gather_x_kernel<<<(BN_ * FOURH + 255) / 256, 256>>>();
    mlp_gemm_kernel<<<dim3(1024 / BUT, BN_ / BMT), 256>>>(W1, b1, 1);
    mlp_gemm_kernel<<<dim3(1024 / BUT, BN_ / BMT), 256>>>(W2, b2, 2);
    mlp_gemm_kernel<<<dim3(1024 / BUT, BN_ / BMT), 256>>>(W3, b3, 3);
    final_logits_kernel<<<BN_, 96>>>(W4, b4, out);
}

// round 10
// speedup vs baseline: 1.1576x; 1.0965x over previous
#include <cuda_runtime.h>
#include <cuda_fp16.h>
#include <math.h>
#include <stdint.h>

// ---------------------------------------------------------------------------
// Problem constants
#define BN_   256
#define TN_   256
#define DN_   300
#define HN_   512
#define XPAD  320
#define KPAD  832
#define NCHX  5
#define NCHS  8
#define FOURH 2048

// ---------------------------------------------------------------------------
// Scratch (device globals)
__device__ __half g_xhi[2ll * BN_ * TN_ * XPAD];
__device__ __half g_xlo[2ll * BN_ * TN_ * XPAD];
__device__ __half g_whi[4ll * FOURH * KPAD];
__device__ __half g_wlo[4ll * FOURH * KPAD];
__device__ float  g_bp [4 * FOURH];
__device__ __half g_hhi[2ll * 4 * BN_ * HN_];
__device__ __half g_hlo[2ll * 4 * BN_ * HN_];
__device__ float  g_c  [4][BN_][HN_];
__device__ float  g_x  [BN_ * FOURH];
__device__ float  g_m1[BN_ * 1024];
__device__ float  g_m2[BN_ * 1024];
__device__ float  g_m3[BN_ * 1024];

#define XZ_PER (2ll * TN_ * BN_ * FOURH)
__device__ float g_xzA[XZ_PER];
__device__ float g_xzB[XZ_PER];

__device__ __forceinline__ float sigmoidf_(float v) { return 1.0f / (1.0f + expf(-v)); }

__device__ __forceinline__ uint32_t smem_u32(const void* p) {
    uint32_t a;
    asm("{ .reg .u64 t; cvta.to.shared.u64 t, %1; cvt.u32.u64 %0, t; }" : "=r"(a) : "l"(p));
    return a;
}
__device__ __forceinline__ void cp16(uint32_t dst, const void* src) {
    asm volatile("cp.async.cg.shared.global [%0], [%1], 16;" :: "r"(dst), "l"(src));
}
#define CP_COMMIT() asm volatile("cp.async.commit_group;" ::: "memory")
#define CP_WAIT(N)  asm volatile("cp.async.wait_group %0;" :: "n"(N) : "memory")

#define LDSM_X4(r0, r1, r2, r3, addr)                                         \
    asm volatile("ldmatrix.sync.aligned.m8n8.x4.shared.b16 {%0,%1,%2,%3}, [%4];" \
        : "=r"(r0), "=r"(r1), "=r"(r2), "=r"(r3) : "r"(addr))

#define MMA16816(d, a, b)                                                     \
    asm volatile("mma.sync.aligned.m16n8k16.row.col.f32.f16.f16.f32 "         \
        "{%0,%1,%2,%3}, {%4,%5,%6,%7}, {%8,%9}, {%0,%1,%2,%3};"               \
        : "+f"((d)[0]), "+f"((d)[1]), "+f"((d)[2]), "+f"((d)[3])              \
        : "r"((a)[0]), "r"((a)[1]), "r"((a)[2]), "r"((a)[3]),                 \
          "r"((b)[0]), "r"((b)[1]))

#define MMA16816H(d, a, b)                                                    \
    asm volatile("mma.sync.aligned.m16n8k16.row.col.f16.f16.f16.f16 "         \
        "{%0,%1}, {%2,%3,%4,%5}, {%6,%7}, {%0,%1};"                           \
        : "+r"((d)[0]), "+r"((d)[1])                                          \
        : "r"((a)[0]), "r"((a)[1]), "r"((a)[2]), "r"((a)[3]),                 \
          "r"((b)[0]), "r"((b)[1]))

// ---------------------------------------------------------------------------
struct WPtrs { const float* wx[4]; const float* wh[4]; const float* bias[4]; };

#define NXE_ (2ll * BN_ * TN_ * XPAD)
#define NWE_ (4ll * FOURH * KPAD)
#define NHE_ (2ll * 4 * BN_ * HN_)
#define NCE_ (4ll * BN_ * HN_)
#define NBE_ (4ll * FOURH)
#define NTOT_ (NXE_ + NWE_ + NHE_ + NCE_ + NBE_)

__global__ void preproc_all(const float* __restrict__ prem, const float* __restrict__ hyp,
                            WPtrs wp) {
    long long i = (long long)blockIdx.x * blockDim.x + threadIdx.x;
    if (i < NXE_) {
        int k = (int)(i % XPAD);
        long long r = i / XPAD;
        int t = (int)(r % TN_); r /= TN_;
        int b = (int)(r % BN_);
        int inp = (int)(r / BN_);
        float v = 0.0f;
        if (k < DN_) {
            const float* src = inp ? hyp : prem;
            v = src[((long long)b * TN_ + t) * DN_ + k];
        }
        __half h = __float2half(v);
        g_xhi[i] = h;
        g_xlo[i] = __float2half(v - __half2float(h));
        return;
    }
    i -= NXE_;
    if (i < NWE_) {
        int kp = (int)(i % KPAD);
        long long r = i / KPAD;
        int c   = (int)(r % FOURH);
        int seq = (int)(r / FOURH);
        int oc  = (c & 3) * HN_ + (c >> 2);
        float v = 0.0f;
        if (kp < DN_)        v = wp.wx[seq][(long long)kp * FOURH + oc];
        else if (kp >= XPAD) v = wp.wh[seq][(long long)(kp - XPAD) * FOURH + oc];
        __half h = __float2half(v);
        g_whi[i] = h;
        g_wlo[i] = __float2half(v - __half2float(h));
        return;
    }
    i -= NWE_;
    if (i < NHE_) {
        g_hhi[i] = __float2half(0.f);
        g_hlo[i] = __float2half(0.f);
        return;
    }
    i -= NHE_;
    if (i < NCE_) {
        (&g_c[0][0][0])[i] = 0.0f;
        return;
    }
    i -= NCE_;
    if (i < NBE_) {
        int c = (int)(i & (FOURH - 1));
        int seq = (int)(i >> 11);
        g_bp[i] = wp.bias[seq][(c & 3) * HN_ + (c >> 2)];
    }
}

// ---------------------------------------------------------------------------
// xz precompute GEMM (unchanged from R9)
#define XST_BYTES 49152
#define XOFF_AL   16384
#define XOFF_BH   32768
#define XOFF_BL   40960
#define SMEM_XZ   98304

__global__ __launch_bounds__(256) void xz_gemm() {
    extern __shared__ char smem[];
    const uint32_t sbase = smem_u32(smem);
    const int tid  = threadIdx.x;
    const int lane = tid & 31;
    const int wid  = tid >> 5;
    const int warp_m = wid >> 1;
    const int warp_n = wid & 1;

    const int z   = blockIdx.z;
    const int seq = z >> 8;
    const int t   = z & 255;
    const int inp = seq >> 1;
    const int b0  = blockIdx.y * 128;
    const int n0  = blockIdx.x * 64;

    auto load_chunk = [&](int k, int p) {
        const uint32_t st = sbase + (p ? XST_BYTES : 0);
        const int k0 = k * 64;
        #pragma unroll
        for (int j = 0; j < 4; j++) {
            int idx = tid + 256 * j;
            int row = idx >> 3;
            int seg = idx & 7;
            long base = ((long)(inp * BN_ + b0 + row) * TN_ + t) * XPAD + k0 + seg * 8;
            uint32_t dst = st + ((row * 8 + (seg ^ (row & 7))) << 4);
            cp16(dst,           g_xhi + base);
            cp16(dst + XOFF_AL, g_xlo + base);
        }
        #pragma unroll
        for (int j = 0; j < 2; j++) {
            int idx = tid + 256 * j;
            int row = idx >> 3;
            int seg = idx & 7;
            long base = ((long)seq * FOURH + n0 + row) * KPAD + k0 + seg * 8;
            uint32_t dst = st + XOFF_BH + ((row * 8 + (seg ^ (row & 7))) << 4);
            cp16(dst,        g_whi + base);
            cp16(dst + 8192, g_wlo + base);
        }
        CP_COMMIT();
    };

    float acc[2][4][4];
    uint32_t acch[2][4][2];
    #pragma unroll
    for (int mi = 0; mi < 2; mi++)
        #pragma unroll
        for (int ni = 0; ni < 4; ni++) {
            #pragma unroll
            for (int q = 0; q < 4; q++) acc[mi][ni][q] = 0.0f;
            acch[mi][ni][0] = 0u; acch[mi][ni][1] = 0u;
        }

    int arowb[2], arowx[2];
    #pragma unroll
    for (int mi = 0; mi < 2; mi++) {
        int r = warp_m * 32 + mi * 16 + (lane & 15);
        arowb[mi] = r * 128;
        arowx[mi] = r & 7;
    }
    int brow[2], browx[2];
    #pragma unroll
    for (int np = 0; np < 2; np++) {
        int n = warp_n * 32 + np * 16 + ((lane >> 4) << 3) + (lane & 7);
        brow[np]  = n * 128;
        browx[np] = n & 7;
    }
    const int asel = lane >> 4;
    const int bsel = (lane >> 3) & 1;

    load_chunk(0, 0);

    for (int k = 0; k < NCHX; k++) {
        const int p = k & 1;
        if (k + 1 < NCHX) load_chunk(k + 1, p ^ 1);
        if (k + 1 < NCHX) CP_WAIT(1); else CP_WAIT(0);
        __syncthreads();

        const uint32_t st = sbase + (p ? XST_BYTES : 0);
        #pragma unroll
        for (int kk = 0; kk < 4; kk++) {
            uint32_t ah[2][4], al[2][4];
            #pragma unroll
            for (int mi = 0; mi < 2; mi++) {
                int seg = 2 * kk + asel;
                uint32_t off = arowb[mi] + ((seg ^ arowx[mi]) << 4);
                LDSM_X4(ah[mi][0], ah[mi][1], ah[mi][2], ah[mi][3], st + off);
                LDSM_X4(al[mi][0], al[mi][1], al[mi][2], al[mi][3], st + XOFF_AL + off);
            }
            uint32_t bh[2][4], bl[2][4];
            #pragma unroll
            for (int np = 0; np < 2; np++) {
                int seg = 2 * kk + bsel;
                uint32_t off = brow[np] + ((seg ^ browx[np]) << 4);
                LDSM_X4(bh[np][0], bh[np][1], bh[np][2], bh[np][3], st + XOFF_BH + off);
                LDSM_X4(bl[np][0], bl[np][1], bl[np][2], bl[np][3], st + XOFF_BL + off);
            }
            #pragma unroll
            for (int mi = 0; mi < 2; mi++)
                #pragma unroll
                for (int np = 0; np < 2; np++)
                    #pragma unroll
                    for (int h = 0; h < 2; h++) {
                        int ni = np * 2 + h;
                        uint32_t bhf[2] = { bh[np][2 * h], bh[np][2 * h + 1] };
                        uint32_t blf[2] = { bl[np][2 * h], bl[np][2 * h + 1] };
                        MMA16816 (acc[mi][ni],  ah[mi], bhf);
                        MMA16816H(acch[mi][ni], ah[mi], blf);
                        MMA16816H(acch[mi][ni], al[mi], bhf);
                    }
        }
        __syncthreads();
    }

    float* xz = (seq < 2) ? g_xzA : g_xzB;
    const long zb = ((long)(seq & 1) * TN_ + t) * BN_;
    #pragma unroll
    for (int mi = 0; mi < 2; mi++) {
        #pragma unroll
        for (int ni = 0; ni < 4; ni++) {
            float2 c01 = __half22float2(*(__half2*)&acch[mi][ni][0]);
            float2 c23 = __half22float2(*(__half2*)&acch[mi][ni][1]);
            int col = n0 + warp_n * 32 + ni * 8 + 2 * (lane & 3);
            int r0  = b0 + warp_m * 32 + mi * 16 + (lane >> 2);
            float2 v01 = make_float2(acc[mi][ni][0] + c01.x, acc[mi][ni][1] + c01.y);
            float2 v23 = make_float2(acc[mi][ni][2] + c23.x, acc[mi][ni][3] + c23.y);
            *(float2*)&xz[(zb + r0)     * FOURH + col] = v01;
            *(float2*)&xz[(zb + r0 + 8) * FOURH + col] = v23;
        }
    }
}

// ---------------------------------------------------------------------------
// Per-step LSTM, SMEM-staged epilogue. 512 threads, 16 warps (4m x 4n).
// SMEM map (bytes):
//   stage0 @0, stage1 @65536 (each: Ah|Al|Bh|Bl 16KB)
//   xz  @131072 (64KB)  c_in @196608 (16KB)
//   hh_in @212992 (8KB) hl_in @221184 (8KB)
//   bias @229376 (512B) len @229888 (512B)
// Output staging reuses stage0 after final sync: c_out @0 (16KB),
//   hh_out @16384 (8KB), hl_out @24576 (8KB)
#define ST_BYTES 65536
#define OFF_AL   16384
#define OFF_BH   32768
#define OFF_BL   49152
#define OFF_XZ   131072
#define OFF_C    196608
#define OFF_HH   212992
#define OFF_HL   221184
#define OFF_BIAS 229376
#define OFF_LEN  229888
#define SMEM_TOTAL_STEP 230400
#define OUT_C    0
#define OUT_HH   16384
#define OUT_HL   24576

__global__ __launch_bounds__(512) void lstm_step_mma(const int* __restrict__ plen,
                                                     const int* __restrict__ hlen,
                                                     int s) {
    extern __shared__ char smem[];
    const uint32_t sbase = smem_u32(smem);
    const int tid  = threadIdx.x;
    const int lane = tid & 31;
    const int wid  = tid >> 5;
    const int warp_m = wid >> 2;
    const int warp_n = wid & 3;

    const int seq = blockIdx.z;
    const int rev = seq & 1;
    const int t   = rev ? (TN_ - 1 - s) : s;
    const int b0  = blockIdx.y * 128;
    const int n0  = blockIdx.x * 128;
    const int u0  = n0 >> 2;
    const int cur = s & 1;

    const int* __restrict__ len = (seq < 2) ? plen : hlen;
    if (tid < 128) {
        *(float*)(smem + OFF_BIAS + tid * 4) = g_bp[seq * FOURH + n0 + tid];
        *(int*)(smem + OFF_LEN + tid * 4) = len[b0 + tid];
    }

    const long hin_base  = ((long)cur * 4 + seq) * (BN_ * HN_);
    const long hout_base = ((long)(cur ^ 1) * 4 + seq) * (BN_ * HN_);
    const float* __restrict__ xzg = (seq < 2) ? g_xzA : g_xzB;
    const long zb = ((long)(seq & 1) * TN_ + t) * BN_;

    auto load_chunk = [&](int k, int p) {
        const uint32_t st = sbase + (p ? ST_BYTES : 0);
        const int k0 = k * 64;
        #pragma unroll
        for (int j = 0; j < 2; j++) {           // A = h: hi + lo
            int idx = tid + 512 * j;
            int row = idx >> 3;
            int seg = idx & 7;
            long base = hin_base + (long)(b0 + row) * HN_ + k0 + seg * 8;
            uint32_t dst = st + ((row * 8 + (seg ^ (row & 7))) << 4);
            cp16(dst,          g_hhi + base);
            cp16(dst + OFF_AL, g_hlo + base);
        }
        #pragma unroll
        for (int j = 0; j < 2; j++) {           // B = Wh region: hi + lo
            int idx = tid + 512 * j;
            int row = idx >> 3;
            int seg = idx & 7;
            long base = ((long)seq * FOURH + n0 + row) * KPAD + XPAD + k0 + seg * 8;
            uint32_t dst = st + OFF_BH + ((row * 8 + (seg ^ (row & 7))) << 4);
            cp16(dst,         g_whi + base);
            cp16(dst + 16384, g_wlo + base);
        }
        // xz piece k: 16 rows x 128 cols fp32
        {
            int row = (k << 4) + (tid >> 5);
            int seg = tid & 31;
            const float* src = xzg + (zb + b0 + row) * FOURH + n0 + seg * 4;
            cp16(sbase + OFF_XZ + row * 512 + seg * 16, src);
        }
        // c piece k: 16 rows x 32 units fp32 (threads 0..127)
        if (tid < 128) {
            int row = (k << 4) + (tid >> 3);
            int seg = tid & 7;
            cp16(sbase + OFF_C + row * 128 + seg * 16, &g_c[seq][b0 + row][u0 + seg * 4]);
        } else if (tid < 192) {
            // old-h hi piece: 16 rows x 32 cols fp16
            int i2  = tid - 128;
            int row = (k << 4) + (i2 >> 2);
            int sg  = i2 & 3;
            cp16(sbase + OFF_HH + row * 64 + sg * 16,
                 g_hhi + hin_base + (long)(b0 + row) * HN_ + u0 + sg * 8);
        } else if (tid < 256) {
            // old-h lo piece
            int i2  = tid - 192;
            int row = (k << 4) + (i2 >> 2);
            int sg  = i2 & 3;
            cp16(sbase + OFF_HL + row * 64 + sg * 16,
                 g_hlo + hin_base + (long)(b0 + row) * HN_ + u0 + sg * 8);
        }
        CP_COMMIT();
    };

    float acc[2][4][4];
    uint32_t acch[2][4][2];
    #pragma unroll
    for (int mi = 0; mi < 2; mi++)
        #pragma unroll
        for (int ni = 0; ni < 4; ni++) {
            #pragma unroll
            for (int q = 0; q < 4; q++) acc[mi][ni][q] = 0.0f;
            acch[mi][ni][0] = 0u; acch[mi][ni][1] = 0u;
        }

    int arowb[2], arowx[2];
    #pragma unroll
    for (int mi = 0; mi < 2; mi++) {
        int r = warp_m * 32 + mi * 16 + (lane & 15);
        arowb[mi] = r * 128;
        arowx[mi] = r & 7;
    }
    int brow[2], browx[2];
    #pragma unroll
    for (int np = 0; np < 2; np++) {
        int n = warp_n * 32 + np * 16 + ((lane >> 4) << 3) + (lane & 7);
        brow[np]  = n * 128;
        browx[np] = n & 7;
    }
    const int asel = lane >> 4;
    const int bsel = (lane >> 3) & 1;

    load_chunk(0, 0);

    for (int k = 0; k < NCHS; k++) {
        const int p = k & 1;
        if (k + 1 < NCHS) load_chunk(k + 1, p ^ 1);
        if (k + 1 < NCHS) CP_WAIT(1); else CP_WAIT(0);
        __syncthreads();

        const uint32_t st = sbase + (p ? ST_BYTES : 0);
        #pragma unroll
        for (int kk = 0; kk < 4; kk++) {
            uint32_t ah[2][4], al[2][4];
            #pragma unroll
            for (int mi = 0; mi < 2; mi++) {
                int seg = 2 * kk + asel;
                uint32_t off = arowb[mi] + ((seg ^ arowx[mi]) << 4);
                LDSM_X4(ah[mi][0], ah[mi][1], ah[mi][2], ah[mi][3], st + off);
                LDSM_X4(al[mi][0], al[mi][1], al[mi][2], al[mi][3], st + OFF_AL + off);
            }
            uint32_t bh[2][4], bl[2][4];
            #pragma unroll
            for (int np = 0; np < 2; np++) {
                int seg = 2 * kk + bsel;
                uint32_t off = brow[np] + ((seg ^ browx[np]) << 4);
                LDSM_X4(bh[np][0], bh[np][1], bh[np][2], bh[np][3], st + OFF_BH + off);
                LDSM_X4(bl[np][0], bl[np][1], bl[np][2], bl[np][3], st + OFF_BL + off);
            }
            #pragma unroll
            for (int mi = 0; mi < 2; mi++)
                #pragma unroll
                for (int np = 0; np < 2; np++)
                    #pragma unroll
                    for (int h = 0; h < 2; h++) {
                        int ni = np * 2 + h;
                        uint32_t bhf[2] = { bh[np][2 * h], bh[np][2 * h + 1] };
                        uint32_t blf[2] = { bl[np][2 * h], bl[np][2 * h + 1] };
                        MMA16816 (acc[mi][ni],  ah[mi], bhf);
                        MMA16816H(acch[mi][ni], ah[mi], blf);
                        MMA16816H(acch[mi][ni], al[mi], bhf);
                    }
        }
        __syncthreads();
    }

    // ---- epilogue: gates into SMEM, then coalesced global copy ------------
    const float* bias_s = (const float*)(smem + OFF_BIAS);
    const int*   len_s  = (const int*)(smem + OFF_LEN);
    const float* xz_s   = (const float*)(smem + OFF_XZ);
    const float* c_s    = (const float*)(smem + OFF_C);
    const __half* hh_s  = (const __half*)(smem + OFF_HH);
    const __half* hl_s  = (const __half*)(smem + OFF_HL);
    float*  c_out  = (float*)(smem + OUT_C);
    __half* hh_out = (__half*)(smem + OUT_HH);
    __half* hl_out = (__half*)(smem + OUT_HL);
    const bool amain = ((lane & 1) == 0);

    #pragma unroll
    for (int mi = 0; mi < 2; mi++) {
        #pragma unroll
        for (int ni = 0; ni < 4; ni++) {
            float2 c01 = __half22float2(*(__half2*)&acch[mi][ni][0]);
            float2 c23 = __half22float2(*(__half2*)&acch[mi][ni][1]);
            int col_local = warp_n * 32 + ni * 8 + 2 * (lane & 3);
            int rl0 = warp_m * 32 + mi * 16 + (lane >> 2);
            float2 x01 = *(const float2*)&xz_s[rl0 * 128 + col_local];
            float2 x23 = *(const float2*)&xz_s[(rl0 + 8) * 128 + col_local];
            float v0 = acc[mi][ni][0] + c01.x + x01.x + bias_s[col_local];
            float v1 = acc[mi][ni][1] + c01.y + x01.y + bias_s[col_local + 1];
            float v2 = acc[mi][ni][2] + c23.x + x23.x + bias_s[col_local];
            float v3 = acc[mi][ni][3] + c23.y + x23.y + bias_s[col_local + 1];
            float p0 = __shfl_xor_sync(0xffffffffu, v0, 1);
            float p1 = __shfl_xor_sync(0xffffffffu, v1, 1);
            float p2 = __shfl_xor_sync(0xffffffffu, v2, 1);
            float p3 = __shfl_xor_sync(0xffffffffu, v3, 1);
            if (amain) {
                int u_local = col_local >> 2;
                #pragma unroll
                for (int rh = 0; rh < 2; rh++) {
                    int rl = rl0 + rh * 8;
                    float iv = rh ? v2 : v0;
                    float jv = rh ? v3 : v1;
                    float fv = rh ? p2 : p0;
                    float ov = rh ? p3 : p1;
                    bool m = (t < len_s[rl]);
                    float c_old = c_s[rl * 32 + u_local];
                    float nc = c_old * sigmoidf_(fv + 1.0f) + sigmoidf_(iv) * tanhf(jv);
                    float nh = tanhf(nc) * sigmoidf_(ov);
                    c_out[rl * 32 + u_local] = m ? nc : c_old;
                    __half hh, hl;
                    if (m) {
                        hh = __float2half(nh);
                        hl = __float2half(nh - __half2float(hh));
                    } else {
                        hh = hh_s[rl * 32 + u_local];
                        hl = hl_s[rl * 32 + u_local];
                    }
                    hh_out[rl * 32 + u_local] = hh;
                    hl_out[rl * 32 + u_local] = hl;
                }
            }
        }
    }
    __syncthreads();

    // coalesced copy to global: c (1024 x 16B), h hi/lo (512 x 16B each)
    #pragma unroll
    for (int j = 0; j < 2; j++) {
        int i   = tid + 512 * j;
        int row = i >> 3;
        int sg  = i & 7;
        *(float4*)&g_c[seq][b0 + row][u0 + sg * 4] =
            *(const float4*)(smem + OUT_C + row * 128 + sg * 16);
    }
    {
        int row = tid >> 2;
        int sg  = tid & 3;
        long dst = hout_base + (long)(b0 + row) * HN_ + u0 + sg * 8;
        *(uint4*)&g_hhi[dst] = *(const uint4*)(smem + OUT_HH + row * 64 + sg * 16);
        *(uint4*)&g_hlo[dst] = *(const uint4*)(smem + OUT_HL + row * 64 + sg * 16);
    }
}

// ---------------------------------------------------------------------------
// MLP head (fp32)
__global__ void gather_x_kernel() {
    int i = blockIdx.x * blockDim.x + threadIdx.x;
    if (i >= BN_ * FOURH) return;
    int b   = i >> 11;
    int col = i & 2047;
    g_x[i] = g_c[col >> 9][b][col & 511];
}

#define BMT 64
#define BUT 64
#define KT  16
__global__ __launch_bounds__(256) void mlp_gemm_kernel(const float* __restrict__ W,
                                                       const float* __restrict__ bias,
                                                       int layer) {
    const float* A; float* C; int K, N;
    if (layer == 1)      { A = g_x;  C = g_m1; K = 2048; N = 1024; }
    else if (layer == 2) { A = g_m1; C = g_m2; K = 1024; N = 1024; }
    else                 { A = g_m2; C = g_m3; K = 1024; N = 1024; }

    const int m0 = blockIdx.y * BMT;
    const int n0 = blockIdx.x * BUT;
    __shared__ float As[KT][BMT];
    __shared__ float Bs[KT][BUT];
    const int tid = threadIdx.x;
    const int r0  = (tid >> 4) * 4;
    const int nt0 = (tid & 15) * 4;

    float acc[4][4];
    #pragma unroll
    for (int r = 0; r < 4; r++)
        #pragma unroll
        for (int u = 0; u < 4; u++) acc[r][u] = 0.0f;

    for (int k0 = 0; k0 < K; k0 += KT) {
        {
            int r  = tid >> 2;
            int kq = (tid & 3) * 4;
            #pragma unroll
            for (int i = 0; i < 4; i++)
                As[kq + i][r] = A[(m0 + r) * K + k0 + kq + i];
        }
        {
            int kk = tid >> 4;
            int uu = (tid & 15) * 4;
            *(float4*)&Bs[kk][uu] = *(const float4*)(W + (k0 + kk) * N + n0 + uu);
        }
        __syncthreads();
        #pragma unroll
        for (int kk = 0; kk < KT; kk++) {
            float4 a4 = *(const float4*)&As[kk][r0];
            float4 b4 = *(const float4*)&Bs[kk][nt0];
            float av[4] = {a4.x, a4.y, a4.z, a4.w};
            float bv[4] = {b4.x, b4.y, b4.z, b4.w};
            #pragma unroll
            for (int r = 0; r < 4; r++)
                #pragma unroll
                for (int u = 0; u < 4; u++)
                    acc[r][u] = fmaf(av[r], bv[u], acc[r][u]);
        }
        __syncthreads();
    }
    #pragma unroll
    for (int r = 0; r < 4; r++)
        #pragma unroll
        for (int u = 0; u < 4; u++) {
            int n = n0 + nt0 + u;
            C[(m0 + r0 + r) * N + n] = tanhf(acc[r][u] + bias[n]);
        }
}

__global__ void final_logits_kernel(const float* __restrict__ W4,
                                    const float* __restrict__ b4,
                                    float* __restrict__ out) {
    int b    = blockIdx.x;
    int w    = threadIdx.x >> 5;
    int lane = threadIdx.x & 31;
    if (w >= 3) return;
    float sum = 0.0f;
    for (int k = lane; k < 1024; k += 32)
        sum += g_m3[b * 1024 + k] * W4[k * 3 + w];
    #pragma unroll
    for (int off = 16; off; off >>= 1)
        sum += __shfl_down_sync(0xffffffff, sum, off);
    if (lane == 0) out[b * 3 + w] = sum + b4[w];
}

// ---------------------------------------------------------------------------
extern "C" void kernel_launch(void* const* d_in, const int* in_sizes, int n_in,
                              void* d_out, int out_size) {
    const float* premises   = (const float*)d_in[0];
    const float* hypotheses = (const float*)d_in[1];
    const int*   plen       = (const int*)d_in[2];
    const int*   hlen       = (const int*)d_in[3];

    WPtrs wp;
    for (int i = 0; i < 4; i++) {
        wp.wx[i]   = (const float*)d_in[4 + 3 * i + 0];
        wp.wh[i]   = (const float*)d_in[4 + 3 * i + 1];
        wp.bias[i] = (const float*)d_in[4 + 3 * i + 2];
    }
    const float* W1 = (const float*)d_in[16];
    const float* b1 = (const float*)d_in[17];
    const float* W2 = (const float*)d_in[18];
    const float* b2 = (const float*)d_in[19];
    const float* W3 = (const float*)d_in[20];
    const float* b3 = (const float*)d_in[21];
    const float* W4 = (const float*)d_in[22];
    const float* b4 = (const float*)d_in[23];
    float* out = (float*)d_out;

    cudaFuncSetAttribute(lstm_step_mma, cudaFuncAttributeMaxDynamicSharedMemorySize,
                         SMEM_TOTAL_STEP);
    cudaFuncSetAttribute(xz_gemm, cudaFuncAttributeMaxDynamicSharedMemorySize,
                         SMEM_XZ);

    {
        long long n = NTOT_;
        preproc_all<<<(unsigned)((n + 255) / 256), 256>>>(premises, hypotheses, wp);
    }

    xz_gemm<<<dim3(32, 2, 4 * TN_), 256, SMEM_XZ>>>();

    dim3 grid(16, 2, 4);
    for (int s = 0; s < TN_; s++)
        lstm_step_mma<<<grid, 512, SMEM_TOTAL_STEP>>>(plen, hlen, s);

    gather_x_kernel<<<(BN_ * FOURH + 255) / 256, 256>>>();
    mlp_gemm_kernel<<<dim3(1024 / BUT, BN_ / BMT), 256>>>(W1, b1, 1);
    mlp_gemm_kernel<<<dim3(1024 / BUT, BN_ / BMT), 256>>>(W2, b2, 2);
    mlp_gemm_kernel<<<dim3(1024 / BUT, BN_ / BMT), 256>>>(W3, b3, 3);
    final_logits_kernel<<<BN_, 96>>>(W4, b4, out);
}

// round 11
// speedup vs baseline: 1.2920x; 1.1161x over previous
#include <cuda_runtime.h>
#include <cuda_fp16.h>
#include <math.h>
#include <stdint.h>

// ---------------------------------------------------------------------------
// Problem constants
#define BN_   256
#define TN_   256
#define DN_   300
#define HN_   512
#define XPAD  320
#define KPAD  832
#define NCHX  5
#define NCHS  8
#define FOURH 2048

// ---------------------------------------------------------------------------
// Scratch (device globals)
__device__ __half g_xhi[2ll * BN_ * TN_ * XPAD];
__device__ __half g_xlo[2ll * BN_ * TN_ * XPAD];
__device__ __half g_whi[4ll * FOURH * KPAD];
__device__ __half g_wlo[4ll * FOURH * KPAD];
__device__ float  g_bp [4 * FOURH];
__device__ __half g_hhi[2ll * 4 * BN_ * HN_];
__device__ __half g_hlo[2ll * 4 * BN_ * HN_];
__device__ float  g_c  [4][BN_][HN_];
__device__ float  g_x  [BN_ * FOURH];
__device__ float  g_m1[BN_ * 1024];
__device__ float  g_m2[BN_ * 1024];
__device__ float  g_m3[BN_ * 1024];

#define XZ_PER (2ll * TN_ * BN_ * FOURH)
__device__ float g_xzA[XZ_PER];
__device__ float g_xzB[XZ_PER];

__device__ __forceinline__ float sig_(float x) {
    return __fdividef(1.0f, 1.0f + __expf(-x));
}
__device__ __forceinline__ float tanh_(float x) {
    float ax = fabsf(x);
    float e  = __expf(-2.0f * ax);
    float r  = __fdividef(1.0f - e, 1.0f + e);
    return copysignf(r, x);
}

__device__ __forceinline__ uint32_t smem_u32(const void* p) {
    uint32_t a;
    asm("{ .reg .u64 t; cvta.to.shared.u64 t, %1; cvt.u32.u64 %0, t; }" : "=r"(a) : "l"(p));
    return a;
}
__device__ __forceinline__ void cp16(uint32_t dst, const void* src) {
    asm volatile("cp.async.cg.shared.global [%0], [%1], 16;" :: "r"(dst), "l"(src));
}
#define CP_COMMIT() asm volatile("cp.async.commit_group;" ::: "memory")
#define CP_WAIT(N)  asm volatile("cp.async.wait_group %0;" :: "n"(N) : "memory")

#define LDSM_X4(r0, r1, r2, r3, addr)                                         \
    asm volatile("ldmatrix.sync.aligned.m8n8.x4.shared.b16 {%0,%1,%2,%3}, [%4];" \
        : "=r"(r0), "=r"(r1), "=r"(r2), "=r"(r3) : "r"(addr))

#define MMA16816(d, a, b)                                                     \
    asm volatile("mma.sync.aligned.m16n8k16.row.col.f32.f16.f16.f32 "         \
        "{%0,%1,%2,%3}, {%4,%5,%6,%7}, {%8,%9}, {%0,%1,%2,%3};"               \
        : "+f"((d)[0]), "+f"((d)[1]), "+f"((d)[2]), "+f"((d)[3])              \
        : "r"((a)[0]), "r"((a)[1]), "r"((a)[2]), "r"((a)[3]),                 \
          "r"((b)[0]), "r"((b)[1]))

#define MMA16816H(d, a, b)                                                    \
    asm volatile("mma.sync.aligned.m16n8k16.row.col.f16.f16.f16.f16 "         \
        "{%0,%1}, {%2,%3,%4,%5}, {%6,%7}, {%0,%1};"                           \
        : "+r"((d)[0]), "+r"((d)[1])                                          \
        : "r"((a)[0]), "r"((a)[1]), "r"((a)[2]), "r"((a)[3]),                 \
          "r"((b)[0]), "r"((b)[1]))

// ---------------------------------------------------------------------------
struct WPtrs { const float* wx[4]; const float* wh[4]; const float* bias[4]; };

#define NXE_ (2ll * BN_ * TN_ * XPAD)
#define NWE_ (4ll * FOURH * KPAD)
#define NHE_ (2ll * 4 * BN_ * HN_)
#define NCE_ (4ll * BN_ * HN_)
#define NBE_ (4ll * FOURH)
#define NTOT_ (NXE_ + NWE_ + NHE_ + NCE_ + NBE_)

__global__ void preproc_all(const float* __restrict__ prem, const float* __restrict__ hyp,
                            WPtrs wp) {
    long long i = (long long)blockIdx.x * blockDim.x + threadIdx.x;
    if (i < NXE_) {
        int k = (int)(i % XPAD);
        long long r = i / XPAD;
        int t = (int)(r % TN_); r /= TN_;
        int b = (int)(r % BN_);
        int inp = (int)(r / BN_);
        float v = 0.0f;
        if (k < DN_) {
            const float* src = inp ? hyp : prem;
            v = src[((long long)b * TN_ + t) * DN_ + k];
        }
        __half h = __float2half(v);
        g_xhi[i] = h;
        g_xlo[i] = __float2half(v - __half2float(h));
        return;
    }
    i -= NXE_;
    if (i < NWE_) {
        int kp = (int)(i % KPAD);
        long long r = i / KPAD;
        int c   = (int)(r % FOURH);
        int seq = (int)(r / FOURH);
        int oc  = (c & 3) * HN_ + (c >> 2);
        float v = 0.0f;
        if (kp < DN_)        v = wp.wx[seq][(long long)kp * FOURH + oc];
        else if (kp >= XPAD) v = wp.wh[seq][(long long)(kp - XPAD) * FOURH + oc];
        __half h = __float2half(v);
        g_whi[i] = h;
        g_wlo[i] = __float2half(v - __half2float(h));
        return;
    }
    i -= NWE_;
    if (i < NHE_) {
        g_hhi[i] = __float2half(0.f);
        g_hlo[i] = __float2half(0.f);
        return;
    }
    i -= NHE_;
    if (i < NCE_) {
        (&g_c[0][0][0])[i] = 0.0f;
        return;
    }
    i -= NCE_;
    if (i < NBE_) {
        int c = (int)(i & (FOURH - 1));
        int seq = (int)(i >> 11);
        g_bp[i] = wp.bias[seq][(c & 3) * HN_ + (c >> 2)];
    }
}

// ---------------------------------------------------------------------------
// xz precompute GEMM (unchanged)
#define XST_BYTES 49152
#define XOFF_AL   16384
#define XOFF_BH   32768
#define XOFF_BL   40960
#define SMEM_XZ   98304

__global__ __launch_bounds__(256) void xz_gemm() {
    extern __shared__ char smem[];
    const uint32_t sbase = smem_u32(smem);
    const int tid  = threadIdx.x;
    const int lane = tid & 31;
    const int wid  = tid >> 5;
    const int warp_m = wid >> 1;
    const int warp_n = wid & 1;

    const int z   = blockIdx.z;
    const int seq = z >> 8;
    const int t   = z & 255;
    const int inp = seq >> 1;
    const int b0  = blockIdx.y * 128;
    const int n0  = blockIdx.x * 64;

    auto load_chunk = [&](int k, int p) {
        const uint32_t st = sbase + (p ? XST_BYTES : 0);
        const int k0 = k * 64;
        #pragma unroll
        for (int j = 0; j < 4; j++) {
            int idx = tid + 256 * j;
            int row = idx >> 3;
            int seg = idx & 7;
            long base = ((long)(inp * BN_ + b0 + row) * TN_ + t) * XPAD + k0 + seg * 8;
            uint32_t dst = st + ((row * 8 + (seg ^ (row & 7))) << 4);
            cp16(dst,           g_xhi + base);
            cp16(dst + XOFF_AL, g_xlo + base);
        }
        #pragma unroll
        for (int j = 0; j < 2; j++) {
            int idx = tid + 256 * j;
            int row = idx >> 3;
            int seg = idx & 7;
            long base = ((long)seq * FOURH + n0 + row) * KPAD + k0 + seg * 8;
            uint32_t dst = st + XOFF_BH + ((row * 8 + (seg ^ (row & 7))) << 4);
            cp16(dst,        g_whi + base);
            cp16(dst + 8192, g_wlo + base);
        }
        CP_COMMIT();
    };

    float acc[2][4][4];
    uint32_t acch[2][4][2];
    #pragma unroll
    for (int mi = 0; mi < 2; mi++)
        #pragma unroll
        for (int ni = 0; ni < 4; ni++) {
            #pragma unroll
            for (int q = 0; q < 4; q++) acc[mi][ni][q] = 0.0f;
            acch[mi][ni][0] = 0u; acch[mi][ni][1] = 0u;
        }

    int arowb[2], arowx[2];
    #pragma unroll
    for (int mi = 0; mi < 2; mi++) {
        int r = warp_m * 32 + mi * 16 + (lane & 15);
        arowb[mi] = r * 128;
        arowx[mi] = r & 7;
    }
    int brow[2], browx[2];
    #pragma unroll
    for (int np = 0; np < 2; np++) {
        int n = warp_n * 32 + np * 16 + ((lane >> 4) << 3) + (lane & 7);
        brow[np]  = n * 128;
        browx[np] = n & 7;
    }
    const int asel = lane >> 4;
    const int bsel = (lane >> 3) & 1;

    load_chunk(0, 0);

    for (int k = 0; k < NCHX; k++) {
        const int p = k & 1;
        if (k + 1 < NCHX) load_chunk(k + 1, p ^ 1);
        if (k + 1 < NCHX) CP_WAIT(1); else CP_WAIT(0);
        __syncthreads();

        const uint32_t st = sbase + (p ? XST_BYTES : 0);
        #pragma unroll
        for (int kk = 0; kk < 4; kk++) {
            uint32_t ah[2][4], al[2][4];
            #pragma unroll
            for (int mi = 0; mi < 2; mi++) {
                int seg = 2 * kk + asel;
                uint32_t off = arowb[mi] + ((seg ^ arowx[mi]) << 4);
                LDSM_X4(ah[mi][0], ah[mi][1], ah[mi][2], ah[mi][3], st + off);
                LDSM_X4(al[mi][0], al[mi][1], al[mi][2], al[mi][3], st + XOFF_AL + off);
            }
            uint32_t bh[2][4], bl[2][4];
            #pragma unroll
            for (int np = 0; np < 2; np++) {
                int seg = 2 * kk + bsel;
                uint32_t off = brow[np] + ((seg ^ browx[np]) << 4);
                LDSM_X4(bh[np][0], bh[np][1], bh[np][2], bh[np][3], st + XOFF_BH + off);
                LDSM_X4(bl[np][0], bl[np][1], bl[np][2], bl[np][3], st + XOFF_BL + off);
            }
            #pragma unroll
            for (int mi = 0; mi < 2; mi++)
                #pragma unroll
                for (int np = 0; np < 2; np++)
                    #pragma unroll
                    for (int h = 0; h < 2; h++) {
                        int ni = np * 2 + h;
                        uint32_t bhf[2] = { bh[np][2 * h], bh[np][2 * h + 1] };
                        uint32_t blf[2] = { bl[np][2 * h], bl[np][2 * h + 1] };
                        MMA16816 (acc[mi][ni],  ah[mi], bhf);
                        MMA16816H(acch[mi][ni], ah[mi], blf);
                        MMA16816H(acch[mi][ni], al[mi], bhf);
                    }
        }
        __syncthreads();
    }

    float* xz = (seq < 2) ? g_xzA : g_xzB;
    const long zb = ((long)(seq & 1) * TN_ + t) * BN_;
    #pragma unroll
    for (int mi = 0; mi < 2; mi++) {
        #pragma unroll
        for (int ni = 0; ni < 4; ni++) {
            float2 c01 = __half22float2(*(__half2*)&acch[mi][ni][0]);
            float2 c23 = __half22float2(*(__half2*)&acch[mi][ni][1]);
            int col = n0 + warp_n * 32 + ni * 8 + 2 * (lane & 3);
            int r0  = b0 + warp_m * 32 + mi * 16 + (lane >> 2);
            float2 v01 = make_float2(acc[mi][ni][0] + c01.x, acc[mi][ni][1] + c01.y);
            float2 v23 = make_float2(acc[mi][ni][2] + c23.x, acc[mi][ni][3] + c23.y);
            *(float2*)&xz[(zb + r0)     * FOURH + col] = v01;
            *(float2*)&xz[(zb + r0 + 8) * FOURH + col] = v23;
        }
    }
}

// ---------------------------------------------------------------------------
// Per-step LSTM. 512 threads, 16 warps (4m x 4n). Balanced SMEM epilogue:
// fragments -> swizzled z-buffer (stage0) -> all threads compute gates ->
// SMEM out buffers (stage1) -> coalesced global copy.
#define ST_BYTES 65536
#define OFF_AL   16384
#define OFF_BH   32768
#define OFF_BL   49152
#define OFF_XZ   131072
#define OFF_C    196608
#define OFF_HH   212992
#define OFF_HL   221184
#define OFF_BIAS 229376
#define OFF_LEN  229888
#define SMEM_TOTAL_STEP 230400
// z buffer reuses stage0 [0..65536); out buffers reuse stage1:
#define OUT_C    65536
#define OUT_HH   81920
#define OUT_HL   90112

__global__ __launch_bounds__(512) void lstm_step_mma(const int* __restrict__ plen,
                                                     const int* __restrict__ hlen,
                                                     int s) {
    extern __shared__ char smem[];
    const uint32_t sbase = smem_u32(smem);
    const int tid  = threadIdx.x;
    const int lane = tid & 31;
    const int wid  = tid >> 5;
    const int warp_m = wid >> 2;
    const int warp_n = wid & 3;

    const int seq = blockIdx.z;
    const int rev = seq & 1;
    const int t   = rev ? (TN_ - 1 - s) : s;
    const int b0  = blockIdx.y * 128;
    const int n0  = blockIdx.x * 128;
    const int u0  = n0 >> 2;
    const int cur = s & 1;

    const int* __restrict__ len = (seq < 2) ? plen : hlen;
    if (tid < 128) {
        *(float*)(smem + OFF_BIAS + tid * 4) = g_bp[seq * FOURH + n0 + tid];
        *(int*)(smem + OFF_LEN + tid * 4) = len[b0 + tid];
    }

    const long hin_base  = ((long)cur * 4 + seq) * (BN_ * HN_);
    const long hout_base = ((long)(cur ^ 1) * 4 + seq) * (BN_ * HN_);
    const float* __restrict__ xzg = (seq < 2) ? g_xzA : g_xzB;
    const long zb = ((long)(seq & 1) * TN_ + t) * BN_;

    auto load_chunk = [&](int k, int p) {
        const uint32_t st = sbase + (p ? ST_BYTES : 0);
        const int k0 = k * 64;
        #pragma unroll
        for (int j = 0; j < 2; j++) {           // A = h: hi + lo
            int idx = tid + 512 * j;
            int row = idx >> 3;
            int seg = idx & 7;
            long base = hin_base + (long)(b0 + row) * HN_ + k0 + seg * 8;
            uint32_t dst = st + ((row * 8 + (seg ^ (row & 7))) << 4);
            cp16(dst,          g_hhi + base);
            cp16(dst + OFF_AL, g_hlo + base);
        }
        #pragma unroll
        for (int j = 0; j < 2; j++) {           // B = Wh region: hi + lo
            int idx = tid + 512 * j;
            int row = idx >> 3;
            int seg = idx & 7;
            long base = ((long)seq * FOURH + n0 + row) * KPAD + XPAD + k0 + seg * 8;
            uint32_t dst = st + OFF_BH + ((row * 8 + (seg ^ (row & 7))) << 4);
            cp16(dst,         g_whi + base);
            cp16(dst + 16384, g_wlo + base);
        }
        // xz piece k: 16 rows x 128 cols fp32
        {
            int row = (k << 4) + (tid >> 5);
            int seg = tid & 31;
            const float* src = xzg + (zb + b0 + row) * FOURH + n0 + seg * 4;
            cp16(sbase + OFF_XZ + row * 512 + seg * 16, src);
        }
        // c piece k (threads 0..127); old-h pieces (threads 128..255)
        if (tid < 128) {
            int row = (k << 4) + (tid >> 3);
            int seg = tid & 7;
            cp16(sbase + OFF_C + row * 128 + seg * 16, &g_c[seq][b0 + row][u0 + seg * 4]);
        } else if (tid < 192) {
            int i2  = tid - 128;
            int row = (k << 4) + (i2 >> 2);
            int sg  = i2 & 3;
            cp16(sbase + OFF_HH + row * 64 + sg * 16,
                 g_hhi + hin_base + (long)(b0 + row) * HN_ + u0 + sg * 8);
        } else if (tid < 256) {
            int i2  = tid - 192;
            int row = (k << 4) + (i2 >> 2);
            int sg  = i2 & 3;
            cp16(sbase + OFF_HL + row * 64 + sg * 16,
                 g_hlo + hin_base + (long)(b0 + row) * HN_ + u0 + sg * 8);
        }
        CP_COMMIT();
    };

    float acc[2][4][4];
    uint32_t acch[2][4][2];
    #pragma unroll
    for (int mi = 0; mi < 2; mi++)
        #pragma unroll
        for (int ni = 0; ni < 4; ni++) {
            #pragma unroll
            for (int q = 0; q < 4; q++) acc[mi][ni][q] = 0.0f;
            acch[mi][ni][0] = 0u; acch[mi][ni][1] = 0u;
        }

    int arowb[2], arowx[2];
    #pragma unroll
    for (int mi = 0; mi < 2; mi++) {
        int r = warp_m * 32 + mi * 16 + (lane & 15);
        arowb[mi] = r * 128;
        arowx[mi] = r & 7;
    }
    int brow[2], browx[2];
    #pragma unroll
    for (int np = 0; np < 2; np++) {
        int n = warp_n * 32 + np * 16 + ((lane >> 4) << 3) + (lane & 7);
        brow[np]  = n * 128;
        browx[np] = n & 7;
    }
    const int asel = lane >> 4;
    const int bsel = (lane >> 3) & 1;

    load_chunk(0, 0);

    for (int k = 0; k < NCHS; k++) {
        const int p = k & 1;
        if (k + 1 < NCHS) load_chunk(k + 1, p ^ 1);
        if (k + 1 < NCHS) CP_WAIT(1); else CP_WAIT(0);
        __syncthreads();

        const uint32_t st = sbase + (p ? ST_BYTES : 0);
        #pragma unroll
        for (int kk = 0; kk < 4; kk++) {
            uint32_t ah[2][4], al[2][4];
            #pragma unroll
            for (int mi = 0; mi < 2; mi++) {
                int seg = 2 * kk + asel;
                uint32_t off = arowb[mi] + ((seg ^ arowx[mi]) << 4);
                LDSM_X4(ah[mi][0], ah[mi][1], ah[mi][2], ah[mi][3], st + off);
                LDSM_X4(al[mi][0], al[mi][1], al[mi][2], al[mi][3], st + OFF_AL + off);
            }
            uint32_t bh[2][4], bl[2][4];
            #pragma unroll
            for (int np = 0; np < 2; np++) {
                int seg = 2 * kk + bsel;
                uint32_t off = brow[np] + ((seg ^ browx[np]) << 4);
                LDSM_X4(bh[np][0], bh[np][1], bh[np][2], bh[np][3], st + OFF_BH + off);
                LDSM_X4(bl[np][0], bl[np][1], bl[np][2], bl[np][3], st + OFF_BL + off);
            }
            #pragma unroll
            for (int mi = 0; mi < 2; mi++)
                #pragma unroll
                for (int np = 0; np < 2; np++)
                    #pragma unroll
                    for (int h = 0; h < 2; h++) {
                        int ni = np * 2 + h;
                        uint32_t bhf[2] = { bh[np][2 * h], bh[np][2 * h + 1] };
                        uint32_t blf[2] = { bl[np][2 * h], bl[np][2 * h + 1] };
                        MMA16816 (acc[mi][ni],  ah[mi], bhf);
                        MMA16816H(acch[mi][ni], ah[mi], blf);
                        MMA16816H(acch[mi][ni], al[mi], bhf);
                    }
        }
        __syncthreads();
    }

    // ---- phase 1: fragments -> swizzled z buffer (stage0, now free) -------
    // z(row, col) at byte: row*512 + (((col>>2) ^ (row&7))<<4) + (col&3)*4
    #pragma unroll
    for (int mi = 0; mi < 2; mi++) {
        #pragma unroll
        for (int ni = 0; ni < 4; ni++) {
            float2 c01 = __half22float2(*(__half2*)&acch[mi][ni][0]);
            float2 c23 = __half22float2(*(__half2*)&acch[mi][ni][1]);
            int col = warp_n * 32 + ni * 8 + 2 * (lane & 3);
            int rl0 = warp_m * 32 + mi * 16 + (lane >> 2);
            float2 v01 = make_float2(acc[mi][ni][0] + c01.x, acc[mi][ni][1] + c01.y);
            float2 v23 = make_float2(acc[mi][ni][2] + c23.x, acc[mi][ni][3] + c23.y);
            int g  = col >> 2;
            int ob = (col & 3) * 4;
            *(float2*)(smem + rl0 * 512 + (((g ^ (rl0 & 7)) << 4) | ob)) = v01;
            int rl1 = rl0 + 8;
            *(float2*)(smem + rl1 * 512 + (((g ^ (rl1 & 7)) << 4) | ob)) = v23;
        }
    }
    __syncthreads();

    // ---- phase 2: all 512 threads, 8 elements each ------------------------
    const float* bias_s = (const float*)(smem + OFF_BIAS);
    const int*   len_s  = (const int*)(smem + OFF_LEN);
    const float* c_s    = (const float*)(smem + OFF_C);
    const __half* hh_s  = (const __half*)(smem + OFF_HH);
    const __half* hl_s  = (const __half*)(smem + OFF_HL);
    float*  c_out  = (float*)(smem + OUT_C);
    __half* hh_out = (__half*)(smem + OUT_HH);
    __half* hl_out = (__half*)(smem + OUT_HL);

    #pragma unroll
    for (int it = 0; it < 8; it++) {
        int e   = it * 512 + tid;
        int row = e >> 5;            // it*16 + (tid>>5): fixed per warp
        int u   = e & 31;
        float4 zv = *(const float4*)(smem + row * 512 + ((u ^ (row & 7)) << 4));
        float4 xv = *(const float4*)(smem + OFF_XZ + row * 512 + u * 16);
        float4 bv = *(const float4*)(bias_s + 4 * u);
        float iv = zv.x + xv.x + bv.x;
        float jv = zv.y + xv.y + bv.y;
        float fv = zv.z + xv.z + bv.z;
        float ov = zv.w + xv.w + bv.w;
        bool  m  = (t < len_s[row]);
        float c_old = c_s[row * 32 + u];
        float nc = c_old * sig_(fv + 1.0f) + sig_(iv) * tanh_(jv);
        float nh = tanh_(nc) * sig_(ov);
        c_out[row * 32 + u] = m ? nc : c_old;
        __half hh, hl;
        if (m) {
            hh = __float2half(nh);
            hl = __float2half(nh - __half2float(hh));
        } else {
            hh = hh_s[row * 32 + u];
            hl = hl_s[row * 32 + u];
        }
        hh_out[row * 32 + u] = hh;
        hl_out[row * 32 + u] = hl;
    }
    __syncthreads();

    // ---- phase 3: coalesced copy to global --------------------------------
    #pragma unroll
    for (int j = 0; j < 2; j++) {
        int i   = tid + 512 * j;
        int row = i >> 3;
        int sg  = i & 7;
        *(float4*)&g_c[seq][b0 + row][u0 + sg * 4] =
            *(const float4*)(smem + OUT_C + row * 128 + sg * 16);
    }
    {
        int row = tid >> 2;
        int sg  = tid & 3;
        long dst = hout_base + (long)(b0 + row) * HN_ + u0 + sg * 8;
        *(uint4*)&g_hhi[dst] = *(const uint4*)(smem + OUT_HH + row * 64 + sg * 16);
        *(uint4*)&g_hlo[dst] = *(const uint4*)(smem + OUT_HL + row * 64 + sg * 16);
    }
}

// ---------------------------------------------------------------------------
// MLP head (fp32)
__global__ void gather_x_kernel() {
    int i = blockIdx.x * blockDim.x + threadIdx.x;
    if (i >= BN_ * FOURH) return;
    int b   = i >> 11;
    int col = i & 2047;
    g_x[i] = g_c[col >> 9][b][col & 511];
}

#define BMT 64
#define BUT 64
#define KT  16
__global__ __launch_bounds__(256) void mlp_gemm_kernel(const float* __restrict__ W,
                                                       const float* __restrict__ bias,
                                                       int layer) {
    const float* A; float* C; int K, N;
    if (layer == 1)      { A = g_x;  C = g_m1; K = 2048; N = 1024; }
    else if (layer == 2) { A = g_m1; C = g_m2; K = 1024; N = 1024; }
    else                 { A = g_m2; C = g_m3; K = 1024; N = 1024; }

    const int m0 = blockIdx.y * BMT;
    const int n0 = blockIdx.x * BUT;
    __shared__ float As[KT][BMT];
    __shared__ float Bs[KT][BUT];
    const int tid = threadIdx.x;
    const int r0  = (tid >> 4) * 4;
    const int nt0 = (tid & 15) * 4;

    float acc[4][4];
    #pragma unroll
    for (int r = 0; r < 4; r++)
        #pragma unroll
        for (int u = 0; u < 4; u++) acc[r][u] = 0.0f;

    for (int k0 = 0; k0 < K; k0 += KT) {
        {
            int r  = tid >> 2;
            int kq = (tid & 3) * 4;
            #pragma unroll
            for (int i = 0; i < 4; i++)
                As[kq + i][r] = A[(m0 + r) * K + k0 + kq + i];
        }
        {
            int kk = tid >> 4;
            int uu = (tid & 15) * 4;
            *(float4*)&Bs[kk][uu] = *(const float4*)(W + (k0 + kk) * N + n0 + uu);
        }
        __syncthreads();
        #pragma unroll
        for (int kk = 0; kk < KT; kk++) {
            float4 a4 = *(const float4*)&As[kk][r0];
            float4 b4 = *(const float4*)&Bs[kk][nt0];
            float av[4] = {a4.x, a4.y, a4.z, a4.w};
            float bv[4] = {b4.x, b4.y, b4.z, b4.w};
            #pragma unroll
            for (int r = 0; r < 4; r++)
                #pragma unroll
                for (int u = 0; u < 4; u++)
                    acc[r][u] = fmaf(av[r], bv[u], acc[r][u]);
        }
        __syncthreads();
    }
    #pragma unroll
    for (int r = 0; r < 4; r++)
        #pragma unroll
        for (int u = 0; u < 4; u++) {
            int n = n0 + nt0 + u;
            C[(m0 + r0 + r) * N + n] = tanhf(acc[r][u] + bias[n]);
        }
}

__global__ void final_logits_kernel(const float* __restrict__ W4,
                                    const float* __restrict__ b4,
                                    float* __restrict__ out) {
    int b    = blockIdx.x;
    int w    = threadIdx.x >> 5;
    int lane = threadIdx.x & 31;
    if (w >= 3) return;
    float sum = 0.0f;
    for (int k = lane; k < 1024; k += 32)
        sum += g_m3[b * 1024 + k] * W4[k * 3 + w];
    #pragma unroll
    for (int off = 16; off; off >>= 1)
        sum += __shfl_down_sync(0xffffffff, sum, off);
    if (lane == 0) out[b * 3 + w] = sum + b4[w];
}

// ---------------------------------------------------------------------------
extern "C" void kernel_launch(void* const* d_in, const int* in_sizes, int n_in,
                              void* d_out, int out_size) {
    const float* premises   = (const float*)d_in[0];
    const float* hypotheses = (const float*)d_in[1];
    const int*   plen       = (const int*)d_in[2];
    const int*   hlen       = (const int*)d_in[3];

    WPtrs wp;
    for (int i = 0; i < 4; i++) {
        wp.wx[i]   = (const float*)d_in[4 + 3 * i + 0];
        wp.wh[i]   = (const float*)d_in[4 + 3 * i + 1];
        wp.bias[i] = (const float*)d_in[4 + 3 * i + 2];
    }
    const float* W1 = (const float*)d_in[16];
    const float* b1 = (const float*)d_in[17];
    const float* W2 = (const float*)d_in[18];
    const float* b2 = (const float*)d_in[19];
    const float* W3 = (const float*)d_in[20];
    const float* b3 = (const float*)d_in[21];
    const float* W4 = (const float*)d_in[22];
    const float* b4 = (const float*)d_in[23];
    float* out = (float*)d_out;

    cudaFuncSetAttribute(lstm_step_mma, cudaFuncAttributeMaxDynamicSharedMemorySize,
                         SMEM_TOTAL_STEP);
    cudaFuncSetAttribute(xz_gemm, cudaFuncAttributeMaxDynamicSharedMemorySize,
                         SMEM_XZ);

    {
        long long n = NTOT_;
        preproc_all<<<(unsigned)((n + 255) / 256), 256>>>(premises, hypotheses, wp);
    }

    xz_gemm<<<dim3(32, 2, 4 * TN_), 256, SMEM_XZ>>>();

    dim3 grid(16, 2, 4);
    for (int s = 0; s < TN_; s++)
        lstm_step_mma<<<grid, 512, SMEM_TOTAL_STEP>>>(plen, hlen, s);

    gather_x_kernel<<<(BN_ * FOURH + 255) / 256, 256>>>();
    mlp_gemm_kernel<<<dim3(1024 / BUT, BN_ / BMT), 256>>>(W1, b1, 1);
    mlp_gemm_kernel<<<dim3(1024 / BUT, BN_ / BMT), 256>>>(W2, b2, 2);
    mlp_gemm_kernel<<<dim3(1024 / BUT, BN_ / BMT), 256>>>(W3, b3, 3);
    final_logits_kernel<<<BN_, 96>>>(W4, b4, out);
}

// round 12
// speedup vs baseline: 1.6019x; 1.2398x over previous
#include <cuda_runtime.h>
#include <cuda_fp16.h>
#include <math.h>
#include <stdint.h>

// ---------------------------------------------------------------------------
// Problem constants
#define BN_   256
#define TN_   256
#define DN_   300
#define HN_   512
#define XPAD  320
#define KPAD  832
#define NCHX  5
#define NCHS  8
#define FOURH 2048

// ---------------------------------------------------------------------------
// Scratch (device globals)
__device__ __half g_xhi[2ll * BN_ * TN_ * XPAD];
__device__ __half g_xlo[2ll * BN_ * TN_ * XPAD];
__device__ __half g_whi[4ll * FOURH * KPAD];
__device__ float  g_bp [4 * FOURH];
__device__ __half g_hhi[2ll * 4 * BN_ * HN_];
__device__ __half g_hlo[2ll * 4 * BN_ * HN_];
__device__ float  g_c  [4][BN_][HN_];
__device__ float  g_x  [BN_ * FOURH];
__device__ float  g_m1[BN_ * 1024];
__device__ float  g_m2[BN_ * 1024];
__device__ float  g_m3[BN_ * 1024];

#define XZ_PER (2ll * TN_ * BN_ * FOURH)
__device__ float g_xzA[XZ_PER];
__device__ float g_xzB[XZ_PER];

__device__ __forceinline__ float sig_(float x) {
    return __fdividef(1.0f, 1.0f + __expf(-x));
}
__device__ __forceinline__ float tanh_(float x) {
    float ax = fabsf(x);
    float e  = __expf(-2.0f * ax);
    float r  = __fdividef(1.0f - e, 1.0f + e);
    return copysignf(r, x);
}

__device__ __forceinline__ uint32_t smem_u32(const void* p) {
    uint32_t a;
    asm("{ .reg .u64 t; cvta.to.shared.u64 t, %1; cvt.u32.u64 %0, t; }" : "=r"(a) : "l"(p));
    return a;
}
__device__ __forceinline__ void cp16(uint32_t dst, const void* src) {
    asm volatile("cp.async.cg.shared.global [%0], [%1], 16;" :: "r"(dst), "l"(src));
}
#define CP_COMMIT() asm volatile("cp.async.commit_group;" ::: "memory")
#define CP_WAIT(N)  asm volatile("cp.async.wait_group %0;" :: "n"(N) : "memory")

#define LDSM_X4(r0, r1, r2, r3, addr)                                         \
    asm volatile("ldmatrix.sync.aligned.m8n8.x4.shared.b16 {%0,%1,%2,%3}, [%4];" \
        : "=r"(r0), "=r"(r1), "=r"(r2), "=r"(r3) : "r"(addr))

#define MMA16816(d, a, b)                                                     \
    asm volatile("mma.sync.aligned.m16n8k16.row.col.f32.f16.f16.f32 "         \
        "{%0,%1,%2,%3}, {%4,%5,%6,%7}, {%8,%9}, {%0,%1,%2,%3};"               \
        : "+f"((d)[0]), "+f"((d)[1]), "+f"((d)[2]), "+f"((d)[3])              \
        : "r"((a)[0]), "r"((a)[1]), "r"((a)[2]), "r"((a)[3]),                 \
          "r"((b)[0]), "r"((b)[1]))

#define MMA16816H(d, a, b)                                                    \
    asm volatile("mma.sync.aligned.m16n8k16.row.col.f16.f16.f16.f16 "         \
        "{%0,%1}, {%2,%3,%4,%5}, {%6,%7}, {%0,%1};"                           \
        : "+r"((d)[0]), "+r"((d)[1])                                          \
        : "r"((a)[0]), "r"((a)[1]), "r"((a)[2]), "r"((a)[3]),                 \
          "r"((b)[0]), "r"((b)[1]))

// ---------------------------------------------------------------------------
struct WPtrs { const float* wx[4]; const float* wh[4]; const float* bias[4]; };

#define NXE_ (2ll * BN_ * TN_ * XPAD)
#define NWE_ (4ll * FOURH * KPAD)
#define NHE_ (2ll * 4 * BN_ * HN_)
#define NCE_ (4ll * BN_ * HN_)
#define NBE_ (4ll * FOURH)
#define NTOT_ (NXE_ + NWE_ + NHE_ + NCE_ + NBE_)

__global__ void preproc_all(const float* __restrict__ prem, const float* __restrict__ hyp,
                            WPtrs wp) {
    long long i = (long long)blockIdx.x * blockDim.x + threadIdx.x;
    if (i < NXE_) {
        int k = (int)(i % XPAD);
        long long r = i / XPAD;
        int t = (int)(r % TN_); r /= TN_;
        int b = (int)(r % BN_);
        int inp = (int)(r / BN_);
        float v = 0.0f;
        if (k < DN_) {
            const float* src = inp ? hyp : prem;
            v = src[((long long)b * TN_ + t) * DN_ + k];
        }
        __half h = __float2half(v);
        g_xhi[i] = h;
        g_xlo[i] = __float2half(v - __half2float(h));
        return;
    }
    i -= NXE_;
    if (i < NWE_) {
        int kp = (int)(i % KPAD);
        long long r = i / KPAD;
        int c   = (int)(r % FOURH);
        int seq = (int)(r / FOURH);
        int oc  = (c & 3) * HN_ + (c >> 2);
        float v = 0.0f;
        if (kp < DN_)        v = wp.wx[seq][(long long)kp * FOURH + oc];
        else if (kp >= XPAD) v = wp.wh[seq][(long long)(kp - XPAD) * FOURH + oc];
        g_whi[i] = __float2half(v);
        return;
    }
    i -= NWE_;
    if (i < NHE_) {
        g_hhi[i] = __float2half(0.f);
        g_hlo[i] = __float2half(0.f);
        return;
    }
    i -= NHE_;
    if (i < NCE_) {
        (&g_c[0][0][0])[i] = 0.0f;
        return;
    }
    i -= NCE_;
    if (i < NBE_) {
        int c = (int)(i & (FOURH - 1));
        int seq = (int)(i >> 11);
        g_bp[i] = wp.bias[seq][(c & 3) * HN_ + (c >> 2)];
    }
}

// ---------------------------------------------------------------------------
// xz precompute GEMM, 2-product (ah*bh f32 + al*bh f16corr)
#define XST_BYTES 40960
#define XOFF_AL   16384
#define XOFF_BH   32768
#define SMEM_XZ   81920

__global__ __launch_bounds__(256) void xz_gemm() {
    extern __shared__ char smem[];
    const uint32_t sbase = smem_u32(smem);
    const int tid  = threadIdx.x;
    const int lane = tid & 31;
    const int wid  = tid >> 5;
    const int warp_m = wid >> 1;
    const int warp_n = wid & 1;

    const int z   = blockIdx.z;
    const int seq = z >> 8;
    const int t   = z & 255;
    const int inp = seq >> 1;
    const int b0  = blockIdx.y * 128;
    const int n0  = blockIdx.x * 64;

    auto load_chunk = [&](int k, int p) {
        const uint32_t st = sbase + (p ? XST_BYTES : 0);
        const int k0 = k * 64;
        #pragma unroll
        for (int j = 0; j < 4; j++) {
            int idx = tid + 256 * j;
            int row = idx >> 3;
            int seg = idx & 7;
            long base = ((long)(inp * BN_ + b0 + row) * TN_ + t) * XPAD + k0 + seg * 8;
            uint32_t dst = st + ((row * 8 + (seg ^ (row & 7))) << 4);
            cp16(dst,           g_xhi + base);
            cp16(dst + XOFF_AL, g_xlo + base);
        }
        #pragma unroll
        for (int j = 0; j < 2; j++) {
            int idx = tid + 256 * j;
            int row = idx >> 3;
            int seg = idx & 7;
            long base = ((long)seq * FOURH + n0 + row) * KPAD + k0 + seg * 8;
            uint32_t dst = st + XOFF_BH + ((row * 8 + (seg ^ (row & 7))) << 4);
            cp16(dst, g_whi + base);
        }
        CP_COMMIT();
    };

    float acc[2][4][4];
    uint32_t acch[2][4][2];
    #pragma unroll
    for (int mi = 0; mi < 2; mi++)
        #pragma unroll
        for (int ni = 0; ni < 4; ni++) {
            #pragma unroll
            for (int q = 0; q < 4; q++) acc[mi][ni][q] = 0.0f;
            acch[mi][ni][0] = 0u; acch[mi][ni][1] = 0u;
        }

    int arowb[2], arowx[2];
    #pragma unroll
    for (int mi = 0; mi < 2; mi++) {
        int r = warp_m * 32 + mi * 16 + (lane & 15);
        arowb[mi] = r * 128;
        arowx[mi] = r & 7;
    }
    int brow[2], browx[2];
    #pragma unroll
    for (int np = 0; np < 2; np++) {
        int n = warp_n * 32 + np * 16 + ((lane >> 4) << 3) + (lane & 7);
        brow[np]  = n * 128;
        browx[np] = n & 7;
    }
    const int asel = lane >> 4;
    const int bsel = (lane >> 3) & 1;

    load_chunk(0, 0);

    for (int k = 0; k < NCHX; k++) {
        const int p = k & 1;
        if (k + 1 < NCHX) load_chunk(k + 1, p ^ 1);
        if (k + 1 < NCHX) CP_WAIT(1); else CP_WAIT(0);
        __syncthreads();

        const uint32_t st = sbase + (p ? XST_BYTES : 0);
        #pragma unroll
        for (int kk = 0; kk < 4; kk++) {
            uint32_t ah[2][4], al[2][4];
            #pragma unroll
            for (int mi = 0; mi < 2; mi++) {
                int seg = 2 * kk + asel;
                uint32_t off = arowb[mi] + ((seg ^ arowx[mi]) << 4);
                LDSM_X4(ah[mi][0], ah[mi][1], ah[mi][2], ah[mi][3], st + off);
                LDSM_X4(al[mi][0], al[mi][1], al[mi][2], al[mi][3], st + XOFF_AL + off);
            }
            uint32_t bh[2][4];
            #pragma unroll
            for (int np = 0; np < 2; np++) {
                int seg = 2 * kk + bsel;
                uint32_t off = brow[np] + ((seg ^ browx[np]) << 4);
                LDSM_X4(bh[np][0], bh[np][1], bh[np][2], bh[np][3], st + XOFF_BH + off);
            }
            #pragma unroll
            for (int mi = 0; mi < 2; mi++)
                #pragma unroll
                for (int np = 0; np < 2; np++)
                    #pragma unroll
                    for (int h = 0; h < 2; h++) {
                        int ni = np * 2 + h;
                        uint32_t bhf[2] = { bh[np][2 * h], bh[np][2 * h + 1] };
                        MMA16816 (acc[mi][ni],  ah[mi], bhf);
                        MMA16816H(acch[mi][ni], al[mi], bhf);
                    }
        }
        __syncthreads();
    }

    float* xz = (seq < 2) ? g_xzA : g_xzB;
    const long zb = ((long)(seq & 1) * TN_ + t) * BN_;
    #pragma unroll
    for (int mi = 0; mi < 2; mi++) {
        #pragma unroll
        for (int ni = 0; ni < 4; ni++) {
            float2 c01 = __half22float2(*(__half2*)&acch[mi][ni][0]);
            float2 c23 = __half22float2(*(__half2*)&acch[mi][ni][1]);
            int col = n0 + warp_n * 32 + ni * 8 + 2 * (lane & 3);
            int r0  = b0 + warp_m * 32 + mi * 16 + (lane >> 2);
            float2 v01 = make_float2(acc[mi][ni][0] + c01.x, acc[mi][ni][1] + c01.y);
            float2 v23 = make_float2(acc[mi][ni][2] + c23.x, acc[mi][ni][3] + c23.y);
            *(float2*)&xz[(zb + r0)     * FOURH + col] = v01;
            *(float2*)&xz[(zb + r0 + 8) * FOURH + col] = v23;
        }
    }
}

// ---------------------------------------------------------------------------
// Per-step LSTM, 2-product MMA. 512 threads, 16 warps (4m x 4n).
// SMEM: stage = Ah(16K)|Al(16K)|Bh(16K) = 48KB, 2 stages @0/@49152.
//   xz @98304 (64KB), c @163840 (16KB), hh @180224 (8KB), hl @188416 (8KB),
//   bias @196608, len @197120. Total 197632.
// z buffer (phase1) reuses [0,65536); out buffers @65536 (c 16K, hh 8K, hl 8K).
#define ST_BYTES 49152
#define OFF_AL   16384
#define OFF_BH   32768
#define OFF_XZ   98304
#define OFF_C    163840
#define OFF_HH   180224
#define OFF_HL   188416
#define OFF_BIAS 196608
#define OFF_LEN  197120
#define SMEM_TOTAL_STEP 197632
#define OUT_C    65536
#define OUT_HH   81920
#define OUT_HL   90112

__global__ __launch_bounds__(512) void lstm_step_mma(const int* __restrict__ plen,
                                                     const int* __restrict__ hlen,
                                                     int s) {
    extern __shared__ char smem[];
    const uint32_t sbase = smem_u32(smem);
    const int tid  = threadIdx.x;
    const int lane = tid & 31;
    const int wid  = tid >> 5;
    const int warp_m = wid >> 2;
    const int warp_n = wid & 3;

    const int seq = blockIdx.z;
    const int rev = seq & 1;
    const int t   = rev ? (TN_ - 1 - s) : s;
    const int b0  = blockIdx.y * 128;
    const int n0  = blockIdx.x * 128;
    const int u0  = n0 >> 2;
    const int cur = s & 1;

    const int* __restrict__ len = (seq < 2) ? plen : hlen;
    if (tid < 128) {
        *(float*)(smem + OFF_BIAS + tid * 4) = g_bp[seq * FOURH + n0 + tid];
        *(int*)(smem + OFF_LEN + tid * 4) = len[b0 + tid];
    }

    const long hin_base  = ((long)cur * 4 + seq) * (BN_ * HN_);
    const long hout_base = ((long)(cur ^ 1) * 4 + seq) * (BN_ * HN_);
    const float* __restrict__ xzg = (seq < 2) ? g_xzA : g_xzB;
    const long zb = ((long)(seq & 1) * TN_ + t) * BN_;

    auto load_chunk = [&](int k, int p) {
        const uint32_t st = sbase + (p ? ST_BYTES : 0);
        const int k0 = k * 64;
        #pragma unroll
        for (int j = 0; j < 2; j++) {           // A = h: hi + lo
            int idx = tid + 512 * j;
            int row = idx >> 3;
            int seg = idx & 7;
            long base = hin_base + (long)(b0 + row) * HN_ + k0 + seg * 8;
            uint32_t dst = st + ((row * 8 + (seg ^ (row & 7))) << 4);
            cp16(dst,          g_hhi + base);
            cp16(dst + OFF_AL, g_hlo + base);
        }
        #pragma unroll
        for (int j = 0; j < 2; j++) {           // B = Wh region: hi only
            int idx = tid + 512 * j;
            int row = idx >> 3;
            int seg = idx & 7;
            long base = ((long)seq * FOURH + n0 + row) * KPAD + XPAD + k0 + seg * 8;
            uint32_t dst = st + OFF_BH + ((row * 8 + (seg ^ (row & 7))) << 4);
            cp16(dst, g_whi + base);
        }
        // xz piece k: 16 rows x 128 cols fp32
        {
            int row = (k << 4) + (tid >> 5);
            int seg = tid & 31;
            const float* src = xzg + (zb + b0 + row) * FOURH + n0 + seg * 4;
            cp16(sbase + OFF_XZ + row * 512 + seg * 16, src);
        }
        // c piece k (threads 0..127); old-h pieces (threads 128..255)
        if (tid < 128) {
            int row = (k << 4) + (tid >> 3);
            int seg = tid & 7;
            cp16(sbase + OFF_C + row * 128 + seg * 16, &g_c[seq][b0 + row][u0 + seg * 4]);
        } else if (tid < 192) {
            int i2  = tid - 128;
            int row = (k << 4) + (i2 >> 2);
            int sg  = i2 & 3;
            cp16(sbase + OFF_HH + row * 64 + sg * 16,
                 g_hhi + hin_base + (long)(b0 + row) * HN_ + u0 + sg * 8);
        } else if (tid < 256) {
            int i2  = tid - 192;
            int row = (k << 4) + (i2 >> 2);
            int sg  = i2 & 3;
            cp16(sbase + OFF_HL + row * 64 + sg * 16,
                 g_hlo + hin_base + (long)(b0 + row) * HN_ + u0 + sg * 8);
        }
        CP_COMMIT();
    };

    float acc[2][4][4];
    uint32_t acch[2][4][2];
    #pragma unroll
    for (int mi = 0; mi < 2; mi++)
        #pragma unroll
        for (int ni = 0; ni < 4; ni++) {
            #pragma unroll
            for (int q = 0; q < 4; q++) acc[mi][ni][q] = 0.0f;
            acch[mi][ni][0] = 0u; acch[mi][ni][1] = 0u;
        }

    int arowb[2], arowx[2];
    #pragma unroll
    for (int mi = 0; mi < 2; mi++) {
        int r = warp_m * 32 + mi * 16 + (lane & 15);
        arowb[mi] = r * 128;
        arowx[mi] = r & 7;
    }
    int brow[2], browx[2];
    #pragma unroll
    for (int np = 0; np < 2; np++) {
        int n = warp_n * 32 + np * 16 + ((lane >> 4) << 3) + (lane & 7);
        brow[np]  = n * 128;
        browx[np] = n & 7;
    }
    const int asel = lane >> 4;
    const int bsel = (lane >> 3) & 1;

    load_chunk(0, 0);

    for (int k = 0; k < NCHS; k++) {
        const int p = k & 1;
        if (k + 1 < NCHS) load_chunk(k + 1, p ^ 1);
        if (k + 1 < NCHS) CP_WAIT(1); else CP_WAIT(0);
        __syncthreads();

        const uint32_t st = sbase + (p ? ST_BYTES : 0);
        #pragma unroll
        for (int kk = 0; kk < 4; kk++) {
            uint32_t ah[2][4], al[2][4];
            #pragma unroll
            for (int mi = 0; mi < 2; mi++) {
                int seg = 2 * kk + asel;
                uint32_t off = arowb[mi] + ((seg ^ arowx[mi]) << 4);
                LDSM_X4(ah[mi][0], ah[mi][1], ah[mi][2], ah[mi][3], st + off);
                LDSM_X4(al[mi][0], al[mi][1], al[mi][2], al[mi][3], st + OFF_AL + off);
            }
            uint32_t bh[2][4];
            #pragma unroll
            for (int np = 0; np < 2; np++) {
                int seg = 2 * kk + bsel;
                uint32_t off = brow[np] + ((seg ^ browx[np]) << 4);
                LDSM_X4(bh[np][0], bh[np][1], bh[np][2], bh[np][3], st + OFF_BH + off);
            }
            #pragma unroll
            for (int mi = 0; mi < 2; mi++)
                #pragma unroll
                for (int np = 0; np < 2; np++)
                    #pragma unroll
                    for (int h = 0; h < 2; h++) {
                        int ni = np * 2 + h;
                        uint32_t bhf[2] = { bh[np][2 * h], bh[np][2 * h + 1] };
                        MMA16816 (acc[mi][ni],  ah[mi], bhf);
                        MMA16816H(acch[mi][ni], al[mi], bhf);
                    }
        }
        __syncthreads();
    }

    // ---- phase 1: fragments -> swizzled z buffer --------------------------
    #pragma unroll
    for (int mi = 0; mi < 2; mi++) {
        #pragma unroll
        for (int ni = 0; ni < 4; ni++) {
            float2 c01 = __half22float2(*(__half2*)&acch[mi][ni][0]);
            float2 c23 = __half22float2(*(__half2*)&acch[mi][ni][1]);
            int col = warp_n * 32 + ni * 8 + 2 * (lane & 3);
            int rl0 = warp_m * 32 + mi * 16 + (lane >> 2);
            float2 v01 = make_float2(acc[mi][ni][0] + c01.x, acc[mi][ni][1] + c01.y);
            float2 v23 = make_float2(acc[mi][ni][2] + c23.x, acc[mi][ni][3] + c23.y);
            int g  = col >> 2;
            int ob = (col & 3) * 4;
            *(float2*)(smem + rl0 * 512 + (((g ^ (rl0 & 7)) << 4) | ob)) = v01;
            int rl1 = rl0 + 8;
            *(float2*)(smem + rl1 * 512 + (((g ^ (rl1 & 7)) << 4) | ob)) = v23;
        }
    }
    __syncthreads();

    // ---- phase 2: all 512 threads, 8 elements each ------------------------
    const float* bias_s = (const float*)(smem + OFF_BIAS);
    const int*   len_s  = (const int*)(smem + OFF_LEN);
    const float* c_s    = (const float*)(smem + OFF_C);
    const __half* hh_s  = (const __half*)(smem + OFF_HH);
    const __half* hl_s  = (const __half*)(smem + OFF_HL);
    float*  c_out  = (float*)(smem + OUT_C);
    __half* hh_out = (__half*)(smem + OUT_HH);
    __half* hl_out = (__half*)(smem + OUT_HL);

    #pragma unroll
    for (int it = 0; it < 8; it++) {
        int e   = it * 512 + tid;
        int row = e >> 5;
        int u   = e & 31;
        float4 zv = *(const float4*)(smem + row * 512 + ((u ^ (row & 7)) << 4));
        float4 xv = *(const float4*)(smem + OFF_XZ + row * 512 + u * 16);
        float4 bv = *(const float4*)(bias_s + 4 * u);
        float iv = zv.x + xv.x + bv.x;
        float jv = zv.y + xv.y + bv.y;
        float fv = zv.z + xv.z + bv.z;
        float ov = zv.w + xv.w + bv.w;
        bool  m  = (t < len_s[row]);
        float c_old = c_s[row * 32 + u];
        float nc = c_old * sig_(fv + 1.0f) + sig_(iv) * tanh_(jv);
        float nh = tanh_(nc) * sig_(ov);
        c_out[row * 32 + u] = m ? nc : c_old;
        __half hh, hl;
        if (m) {
            hh = __float2half(nh);
            hl = __float2half(nh - __half2float(hh));
        } else {
            hh = hh_s[row * 32 + u];
            hl = hl_s[row * 32 + u];
        }
        hh_out[row * 32 + u] = hh;
        hl_out[row * 32 + u] = hl;
    }
    __syncthreads();

    // ---- phase 3: coalesced copy to global --------------------------------
    #pragma unroll
    for (int j = 0; j < 2; j++) {
        int i   = tid + 512 * j;
        int row = i >> 3;
        int sg  = i & 7;
        *(float4*)&g_c[seq][b0 + row][u0 + sg * 4] =
            *(const float4*)(smem + OUT_C + row * 128 + sg * 16);
    }
    {
        int row = tid >> 2;
        int sg  = tid & 3;
        long dst = hout_base + (long)(b0 + row) * HN_ + u0 + sg * 8;
        *(uint4*)&g_hhi[dst] = *(const uint4*)(smem + OUT_HH + row * 64 + sg * 16);
        *(uint4*)&g_hlo[dst] = *(const uint4*)(smem + OUT_HL + row * 64 + sg * 16);
    }
}

// ---------------------------------------------------------------------------
// MLP head (fp32)
__global__ void gather_x_kernel() {
    int i = blockIdx.x * blockDim.x + threadIdx.x;
    if (i >= BN_ * FOURH) return;
    int b   = i >> 11;
    int col = i & 2047;
    g_x[i] = g_c[col >> 9][b][col & 511];
}

#define BMT 64
#define BUT 64
#define KT  16
__global__ __launch_bounds__(256) void mlp_gemm_kernel(const float* __restrict__ W,
                                                       const float* __restrict__ bias,
                                                       int layer) {
    const float* A; float* C; int K, N;
    if (layer == 1)      { A = g_x;  C = g_m1; K = 2048; N = 1024; }
    else if (layer == 2) { A = g_m1; C = g_m2; K = 1024; N = 1024; }
    else                 { A = g_m2; C = g_m3; K = 1024; N = 1024; }

    const int m0 = blockIdx.y * BMT;
    const int n0 = blockIdx.x * BUT;
    __shared__ float As[KT][BMT];
    __shared__ float Bs[KT][BUT];
    const int tid = threadIdx.x;
    const int r0  = (tid >> 4) * 4;
    const int nt0 = (tid & 15) * 4;

    float acc[4][4];
    #pragma unroll
    for (int r = 0; r < 4; r++)
        #pragma unroll
        for (int u = 0; u < 4; u++) acc[r][u] = 0.0f;

    for (int k0 = 0; k0 < K; k0 += KT) {
        {
            int r  = tid >> 2;
            int kq = (tid & 3) * 4;
            #pragma unroll
            for (int i = 0; i < 4; i++)
                As[kq + i][r] = A[(m0 + r) * K + k0 + kq + i];
        }
        {
            int kk = tid >> 4;
            int uu = (tid & 15) * 4;
            *(float4*)&Bs[kk][uu] = *(const float4*)(W + (k0 + kk) * N + n0 + uu);
        }
        __syncthreads();
        #pragma unroll
        for (int kk = 0; kk < KT; kk++) {
            float4 a4 = *(const float4*)&As[kk][r0];
            float4 b4 = *(const float4*)&Bs[kk][nt0];
            float av[4] = {a4.x, a4.y, a4.z, a4.w};
            float bv[4] = {b4.x, b4.y, b4.z, b4.w};
            #pragma unroll
            for (int r = 0; r < 4; r++)
                #pragma unroll
                for (int u = 0; u < 4; u++)
                    acc[r][u] = fmaf(av[r], bv[u], acc[r][u]);
        }
        __syncthreads();
    }
    #pragma unroll
    for (int r = 0; r < 4; r++)
        #pragma unroll
        for (int u = 0; u < 4; u++) {
            int n = n0 + nt0 + u;
            C[(m0 + r0 + r) * N + n] = tanhf(acc[r][u] + bias[n]);
        }
}

__global__ void final_logits_kernel(const float* __restrict__ W4,
                                    const float* __restrict__ b4,
                                    float* __restrict__ out) {
    int b    = blockIdx.x;
    int w    = threadIdx.x >> 5;
    int lane = threadIdx.x & 31;
    if (w >= 3) return;
    float sum = 0.0f;
    for (int k = lane; k < 1024; k += 32)
        sum += g_m3[b * 1024 + k] * W4[k * 3 + w];
    #pragma unroll
    for (int off = 16; off; off >>= 1)
        sum += __shfl_down_sync(0xffffffff, sum, off);
    if (lane == 0) out[b * 3 + w] = sum + b4[w];
}

// ---------------------------------------------------------------------------
extern "C" void kernel_launch(void* const* d_in, const int* in_sizes, int n_in,
                              void* d_out, int out_size) {
    const float* premises   = (const float*)d_in[0];
    const float* hypotheses = (const float*)d_in[1];
    const int*   plen       = (const int*)d_in[2];
    const int*   hlen       = (const int*)d_in[3];

    WPtrs wp;
    for (int i = 0; i < 4; i++) {
        wp.wx[i]   = (const float*)d_in[4 + 3 * i + 0];
        wp.wh[i]   = (const float*)d_in[4 + 3 * i + 1];
        wp.bias[i] = (const float*)d_in[4 + 3 * i + 2];
    }
    const float* W1 = (const float*)d_in[16];
    const float* b1 = (const float*)d_in[17];
    const float* W2 = (const float*)d_in[18];
    const float* b2 = (const float*)d_in[19];
    const float* W3 = (const float*)d_in[20];
    const float* b3 = (const float*)d_in[21];
    const float* W4 = (const float*)d_in[22];
    const float* b4 = (const float*)d_in[23];
    float* out = (float*)d_out;

    cudaFuncSetAttribute(lstm_step_mma, cudaFuncAttributeMaxDynamicSharedMemorySize,
                         SMEM_TOTAL_STEP);
    cudaFuncSetAttribute(xz_gemm, cudaFuncAttributeMaxDynamicSharedMemorySize,
                         SMEM_XZ);

    {
        long long n = NTOT_;
        preproc_all<<<(unsigned)((n + 255) / 256), 256>>>(premises, hypotheses, wp);
    }

    xz_gemm<<<dim3(32, 2, 4 * TN_), 256, SMEM_XZ>>>();

    dim3 grid(16, 2, 4);
    for (int s = 0; s < TN_; s++)
        lstm_step_mma<<<grid, 512, SMEM_TOTAL_STEP>>>(plen, hlen, s);

    gather_x_kernel<<<(BN_ * FOURH + 255) / 256, 256>>>();
    mlp_gemm_kernel<<<dim3(1024 / BUT, BN_ / BMT), 256>>>(W1, b1, 1);
    mlp_gemm_kernel<<<dim3(1024 / BUT, BN_ / BMT), 256>>>(W2, b2, 2);
    mlp_gemm_kernel<<<dim3(1024 / BUT, BN_ / BMT), 256>>>(W3, b3, 3);
    final_logits_kernel<<<BN_, 96>>>(W4, b4, out);
}